// round 13
// baseline (speedup 1.0000x reference)
#include <cuda_runtime.h>
#include <cuda_bf16.h>
#include <math.h>
#include <stdint.h>

#define HIDDEN   2048
#define NHEADS   16
#define NKVHEADS 4
#define HEADDIM  128
#define BATCH    2
#define SEQ      2048
#define MROWS    (BATCH * SEQ)          // 4096
#define KVDIM    (NKVHEADS * HEADDIM)   // 512

#define DEVINL __device__ __forceinline__

// ---------------------------------------------------------------------------
// Scratch
// ---------------------------------------------------------------------------
__device__ __nv_bfloat16 g_Hh[MROWS * HIDDEN], g_Hl[MROWS * HIDDEN];
__device__ __nv_bfloat16 g_Wqt_h[HIDDEN * HIDDEN], g_Wqt_l[HIDDEN * HIDDEN];
__device__ __nv_bfloat16 g_Wkt_h[KVDIM * HIDDEN],  g_Wkt_l[KVDIM * HIDDEN];
__device__ __nv_bfloat16 g_Wvt_h[KVDIM * HIDDEN],  g_Wvt_l[KVDIM * HIDDEN];
__device__ __nv_bfloat16 g_Wot_h[HIDDEN * HIDDEN], g_Wot_l[HIDDEN * HIDDEN];
__device__ float g_qf[MROWS * HIDDEN];
__device__ float g_kf[MROWS * KVDIM];
__device__ float g_vf[MROWS * KVDIM];
__device__ __nv_bfloat16 g_Ah[MROWS * HIDDEN], g_Al[MROWS * HIDDEN];
__device__ __nv_bfloat16 g_Qh[MROWS * HIDDEN], g_Ql[MROWS * HIDDEN];
__device__ __nv_bfloat16 g_Kh[MROWS * KVDIM],  g_Kl[MROWS * KVDIM];
__device__ __nv_bfloat16 g_Vth[BATCH * KVDIM * SEQ], g_Vtl[BATCH * KVDIM * SEQ]; // [z*128+d][s]

// ---------------------------------------------------------------------------
// PTX helpers
// ---------------------------------------------------------------------------
DEVINL unsigned smem_u32(const void* p) { return (unsigned)__cvta_generic_to_shared(p); }

DEVINL void ldsm4(unsigned& r0, unsigned& r1, unsigned& r2, unsigned& r3, unsigned a) {
    asm volatile("ldmatrix.sync.aligned.m8n8.x4.shared.b16 {%0,%1,%2,%3}, [%4];\n"
                 : "=r"(r0), "=r"(r1), "=r"(r2), "=r"(r3) : "r"(a));
}
DEVINL void mma_bf16(float c[4], const unsigned a[4], unsigned b0, unsigned b1) {
    asm volatile(
        "mma.sync.aligned.m16n8k16.row.col.f32.bf16.bf16.f32 "
        "{%0,%1,%2,%3}, {%4,%5,%6,%7}, {%8,%9}, {%0,%1,%2,%3};\n"
        : "+f"(c[0]), "+f"(c[1]), "+f"(c[2]), "+f"(c[3])
        : "r"(a[0]), "r"(a[1]), "r"(a[2]), "r"(a[3]), "r"(b0), "r"(b1));
}
DEVINL unsigned addrA(unsigned base, int lane, int row0, int col0, int pitch) {
    int r = row0 + (lane & 15);
    int c = col0 + ((lane >> 4) << 3);
    return base + (unsigned)(r * pitch + c) * 2u;
}
DEVINL unsigned addrB(unsigned base, int lane, int row0, int col0, int pitch) {
    int r = row0 + ((lane >> 4) << 3) + (lane & 7);
    int c = col0 + (((lane >> 3) & 1) << 3);
    return base + (unsigned)(r * pitch + c) * 2u;
}
DEVINL float ex2f(float x) { float r; asm("ex2.approx.ftz.f32 %0, %1;" : "=f"(r) : "f"(x)); return r; }

DEVINL void cpasync16(unsigned dst, const void* src) {
    asm volatile("cp.async.cg.shared.global [%0], [%1], 16;\n" :: "r"(dst), "l"(src));
}
DEVINL void cp_commit() { asm volatile("cp.async.commit_group;\n" ::); }
DEVINL void cp_wait0()  { asm volatile("cp.async.wait_group 0;\n" ::); }
DEVINL void cp_wait1()  { asm volatile("cp.async.wait_group 1;\n" ::); }

DEVINL void split_bf16(float x, __nv_bfloat16& h, __nv_bfloat16& l) {
    h = __float2bfloat16(x);
    l = __float2bfloat16(x - __bfloat162float(h));
}
DEVINL unsigned pack2(__nv_bfloat16 lo, __nv_bfloat16 hi) {
    return (unsigned)__bfloat16_as_ushort(lo) | ((unsigned)__bfloat16_as_ushort(hi) << 16);
}

// ---------------------------------------------------------------------------
// fp32 -> bf16 hi/lo split (hidden activations)
// ---------------------------------------------------------------------------
__global__ void split_f32(const float* __restrict__ X,
                          __nv_bfloat16* __restrict__ H,
                          __nv_bfloat16* __restrict__ L, int n4)
{
    int i = blockIdx.x * blockDim.x + threadIdx.x;
    if (i >= n4) return;
    float4 v = ((const float4*)X)[i];
    __nv_bfloat16 h0, h1, h2, h3, l0, l1, l2, l3;
    split_bf16(v.x, h0, l0); split_bf16(v.y, h1, l1);
    split_bf16(v.z, h2, l2); split_bf16(v.w, h3, l3);
    *(uint2*)(H + (size_t)i * 4) = make_uint2(pack2(h0, h1), pack2(h2, h3));
    *(uint2*)(L + (size_t)i * 4) = make_uint2(pack2(l0, l1), pack2(l2, l3));
}

// ---------------------------------------------------------------------------
// All four W [K][N] fp32 -> [N][K] bf16 hi/lo in ONE launch (grid.z selects)
// ---------------------------------------------------------------------------
__global__ void transpose_all(
    const float* __restrict__ Wq, const float* __restrict__ Wk,
    const float* __restrict__ Wv, const float* __restrict__ Wo,
    __nv_bfloat16* __restrict__ Wqh, __nv_bfloat16* __restrict__ Wql,
    __nv_bfloat16* __restrict__ Wkh, __nv_bfloat16* __restrict__ Wkl,
    __nv_bfloat16* __restrict__ Wvh, __nv_bfloat16* __restrict__ Wvl,
    __nv_bfloat16* __restrict__ Woh, __nv_bfloat16* __restrict__ Wol)
{
    const int z = blockIdx.z;
    const float* W; __nv_bfloat16 *Th, *Tl; int N;
    if (z == 0)      { W = Wq; Th = Wqh; Tl = Wql; N = HIDDEN; }
    else if (z == 1) { W = Wk; Th = Wkh; Tl = Wkl; N = KVDIM; }
    else if (z == 2) { W = Wv; Th = Wvh; Tl = Wvl; N = KVDIM; }
    else             { W = Wo; Th = Woh; Tl = Wol; N = HIDDEN; }

    int n0 = blockIdx.x * 32, k0 = blockIdx.y * 32;
    if (n0 >= N) return;

    __shared__ float t[32][33];
    int tx = threadIdx.x, ty = threadIdx.y;
#pragma unroll
    for (int i = 0; i < 4; i++)
        t[ty + i * 8][tx] = W[(size_t)(k0 + ty + i * 8) * N + n0 + tx];
    __syncthreads();
#pragma unroll
    for (int i = 0; i < 4; i++) {
        float v = t[tx][ty + i * 8];
        __nv_bfloat16 h, l;
        split_bf16(v, h, l);
        size_t o = (size_t)(n0 + ty + i * 8) * HIDDEN + k0 + tx;
        Th[o] = h; Tl[o] = l;
    }
}

// V [b*S+s][kvh*128+d] fp32 -> Vt [(b*4+kvh)*128+d][s] bf16 hi/lo
__global__ void vt_split(const float* __restrict__ vf,
                         __nv_bfloat16* __restrict__ Th,
                         __nv_bfloat16* __restrict__ Tl)
{
    __shared__ float t[32][33];
    int s0 = blockIdx.x * 32, d0 = blockIdx.y * 32, z = blockIdx.z;
    int b = z >> 2, kvh = z & 3;
    int tx = threadIdx.x, ty = threadIdx.y;
#pragma unroll
    for (int i = 0; i < 4; i++)
        t[ty + i * 8][tx] = vf[(size_t)(b * SEQ + s0 + ty + i * 8) * KVDIM + kvh * 128 + d0 + tx];
    __syncthreads();
#pragma unroll
    for (int i = 0; i < 4; i++) {
        float v = t[tx][ty + i * 8];
        __nv_bfloat16 h, l;
        split_bf16(v, h, l);
        size_t o = (size_t)(z * 128 + d0 + ty + i * 8) * SEQ + s0 + tx;
        Th[o] = h; Tl[o] = l;
    }
}

// ---------------------------------------------------------------------------
// GEMM core (validated): one 128x128 tile of C = (Ah+Al)@(Bh+Bl)^T + bias
// ---------------------------------------------------------------------------
#define KP 40
#define GEMM_TILE_B  (128 * KP * 2)
#define GEMM_STAGE_B (4 * GEMM_TILE_B)
#define GEMM_SMEM    (2 * GEMM_STAGE_B)          // 81920

DEVINL void gemm_tile(
    const __nv_bfloat16* Ah, const __nv_bfloat16* Al,
    const __nv_bfloat16* Bh, const __nv_bfloat16* Bl,
    const float* bias, float* C,
    int m0, int n0loc, int N, int K, char* gsm)
{
    const unsigned sbase = smem_u32(gsm);
    const int tid = threadIdx.x, lane = tid & 31, warp = tid >> 5;
    const int wm = warp >> 2, wn = warp & 3;

    float acc[4][4][4];
#pragma unroll
    for (int i = 0; i < 4; i++)
#pragma unroll
        for (int j = 0; j < 4; j++)
#pragma unroll
            for (int v = 0; v < 4; v++) acc[i][j][v] = 0.f;

    const int nk = K / 32;

    auto issue = [&](int st, int k0) {
        unsigned sb = sbase + (unsigned)st * GEMM_STAGE_B;
#pragma unroll
        for (int l = 0; l < 2; l++) {
            int f = tid + l * 256;
            int row = f >> 2;
            int kc = (f & 3) * 8;
            unsigned so = (unsigned)(row * KP + kc) * 2u;
            size_t goA = (size_t)(m0 + row) * K + k0 + kc;
            size_t goB = (size_t)(n0loc + row) * K + k0 + kc;
            cpasync16(sb + so,                     Ah + goA);
            cpasync16(sb + GEMM_TILE_B + so,       Al + goA);
            cpasync16(sb + 2 * GEMM_TILE_B + so,   Bh + goB);
            cpasync16(sb + 3 * GEMM_TILE_B + so,   Bl + goB);
        }
    };

    issue(0, 0);
    cp_commit();

    for (int kt = 0; kt < nk; kt++) {
        int st = kt & 1;
        if (kt + 1 < nk) { issue(st ^ 1, (kt + 1) * 32); cp_commit(); cp_wait1(); }
        else             { cp_wait0(); }
        __syncthreads();

        unsigned sb  = sbase + (unsigned)st * GEMM_STAGE_B;
        unsigned bAh = sb;
        unsigned bAl = sb + GEMM_TILE_B;
        unsigned bBh = sb + 2 * GEMM_TILE_B;
        unsigned bBl = sb + 3 * GEMM_TILE_B;

#pragma unroll
        for (int ks = 0; ks < 2; ks++) {
            int kb = ks * 16;
            unsigned bh[4][2], bl[4][2];
#pragma unroll
            for (int g = 0; g < 2; g++) {
                unsigned r0, r1, r2, r3;
                ldsm4(r0, r1, r2, r3, addrB(bBh, lane, wn * 32 + g * 16, kb, KP));
                bh[g * 2][0] = r0; bh[g * 2][1] = r1;
                bh[g * 2 + 1][0] = r2; bh[g * 2 + 1][1] = r3;
                ldsm4(r0, r1, r2, r3, addrB(bBl, lane, wn * 32 + g * 16, kb, KP));
                bl[g * 2][0] = r0; bl[g * 2][1] = r1;
                bl[g * 2 + 1][0] = r2; bl[g * 2 + 1][1] = r3;
            }
#pragma unroll
            for (int mf = 0; mf < 4; mf++) {
                unsigned ah[4], al[4];
                ldsm4(ah[0], ah[1], ah[2], ah[3], addrA(bAh, lane, wm * 64 + mf * 16, kb, KP));
                ldsm4(al[0], al[1], al[2], al[3], addrA(bAl, lane, wm * 64 + mf * 16, kb, KP));
#pragma unroll
                for (int nf = 0; nf < 4; nf++) {
                    mma_bf16(acc[mf][nf], ah, bh[nf][0], bh[nf][1]);
                    mma_bf16(acc[mf][nf], ah, bl[nf][0], bl[nf][1]);
                    mma_bf16(acc[mf][nf], al, bh[nf][0], bh[nf][1]);
                }
            }
        }
        __syncthreads();
    }

    const int rb = m0 + wm * 64, cb = n0loc + wn * 32;
#pragma unroll
    for (int mf = 0; mf < 4; mf++)
#pragma unroll
        for (int nf = 0; nf < 4; nf++) {
            int r = rb + mf * 16 + (lane >> 2);
            int c = cb + nf * 8 + (lane & 3) * 2;
            float b0 = bias[c], b1 = bias[c + 1];
            *(float2*)&C[(size_t)r * N + c] =
                make_float2(acc[mf][nf][0] + b0, acc[mf][nf][1] + b1);
            *(float2*)&C[(size_t)(r + 8) * N + c] =
                make_float2(acc[mf][nf][2] + b0, acc[mf][nf][3] + b1);
        }
}

// Merged Q/K/V projection: one launch, grid (24, 32).
__global__ __launch_bounds__(256) void gemm_qkv(
    const __nv_bfloat16* __restrict__ Ah, const __nv_bfloat16* __restrict__ Al,
    const __nv_bfloat16* __restrict__ Wqh, const __nv_bfloat16* __restrict__ Wql,
    const __nv_bfloat16* __restrict__ Wkh, const __nv_bfloat16* __restrict__ Wkl,
    const __nv_bfloat16* __restrict__ Wvh, const __nv_bfloat16* __restrict__ Wvl,
    const float* __restrict__ bq, const float* __restrict__ bk, const float* __restrict__ bv,
    float* __restrict__ qf, float* __restrict__ kf, float* __restrict__ vf)
{
    extern __shared__ char gsm[];
    const int nt = blockIdx.x;
    const int m0 = blockIdx.y * 128;
    const __nv_bfloat16 *Bh, *Bl; const float* bias; float* C; int N, n0;
    if (nt < 16)      { Bh = Wqh; Bl = Wql; bias = bq; C = qf; N = HIDDEN; n0 = nt * 128; }
    else if (nt < 20) { Bh = Wkh; Bl = Wkl; bias = bk; C = kf; N = KVDIM;  n0 = (nt - 16) * 128; }
    else              { Bh = Wvh; Bl = Wvl; bias = bv; C = vf; N = KVDIM;  n0 = (nt - 20) * 128; }
    gemm_tile(Ah, Al, Bh, Bl, bias, C, m0, n0, N, HIDDEN, gsm);
}

__global__ __launch_bounds__(256) void gemm_bf16x3(
    const __nv_bfloat16* __restrict__ Ah, const __nv_bfloat16* __restrict__ Al,
    const __nv_bfloat16* __restrict__ Bh, const __nv_bfloat16* __restrict__ Bl,
    const float* __restrict__ bias, float* __restrict__ C,
    int M, int N, int K)
{
    extern __shared__ char gsm[];
    gemm_tile(Ah, Al, Bh, Bl, bias, C, blockIdx.y * 128, blockIdx.x * 128, N, K, gsm);
}

// ---------------------------------------------------------------------------
// RoPE on Q, K fp32 -> bf16 hi/lo splits (fused); double-precision cos/sin
// (validated numerics)
// ---------------------------------------------------------------------------
__global__ __launch_bounds__(128) void rope_split(
    const int* __restrict__ pos_ids,
    const float* __restrict__ qf, const float* __restrict__ kf,
    __nv_bfloat16* __restrict__ Qh, __nv_bfloat16* __restrict__ Ql,
    __nv_bfloat16* __restrict__ Kh, __nv_bfloat16* __restrict__ Kl)
{
    const int bs = blockIdx.x;
    const int t = threadIdx.x;
    __shared__ float cs[64], sn[64];
    if (t < 64) {
        double pos = (double)pos_ids[bs];
        double inv = exp(-((double)t / 64.0) * 13.815510557964274);
        double fr = pos * inv;
        cs[t] = (float)cos(fr);
        sn[t] = (float)sin(fr);
    }
    __syncthreads();

    const float* q = qf + (size_t)bs * HIDDEN;
#pragma unroll
    for (int p = t; p < NHEADS * 64; p += 128) {
        int h = p >> 6, d = p & 63;
        size_t base = (size_t)bs * HIDDEN + h * HEADDIM;
        float x0 = q[h * HEADDIM + d], x1 = q[h * HEADDIM + d + 64];
        float y0 = x0 * cs[d] - x1 * sn[d];
        float y1 = x1 * cs[d] + x0 * sn[d];
        __nv_bfloat16 h0, l0, h1, l1;
        split_bf16(y0, h0, l0); split_bf16(y1, h1, l1);
        Qh[base + d] = h0; Ql[base + d] = l0;
        Qh[base + d + 64] = h1; Ql[base + d + 64] = l1;
    }
    const float* k = kf + (size_t)bs * KVDIM;
#pragma unroll
    for (int p = t; p < NKVHEADS * 64; p += 128) {
        int h = p >> 6, d = p & 63;
        size_t base = (size_t)bs * KVDIM + h * HEADDIM;
        float x0 = k[h * HEADDIM + d], x1 = k[h * HEADDIM + d + 64];
        float y0 = x0 * cs[d] - x1 * sn[d];
        float y1 = x1 * cs[d] + x0 * sn[d];
        __nv_bfloat16 h0, l0, h1, l1;
        split_bf16(y0, h0, l0); split_bf16(y1, h1, l1);
        Kh[base + d] = h0; Kl[base + d] = l0;
        Kh[base + d + 64] = h1; Kl[base + d + 64] = l1;
    }
}

// ---------------------------------------------------------------------------
// Tensor-core causal flash attention (bf16x3).
// 128 threads / 4 warps; CTA = 64 q rows; warp owns 16 q rows; KV tile 32.
// smem = 72704 B -> 3 CTAs/SM (launch_bounds(128,3): 170-reg budget, no spill).
// ---------------------------------------------------------------------------
#define QP2 136
#define VP2 40
#define ATTN_SMEM ((2 * 64 * QP2 + 2 * 32 * QP2 + 2 * 128 * VP2) * 2)  // 72704

__global__ __launch_bounds__(128, 3) void attn_mma(
    const __nv_bfloat16* __restrict__ Qh, const __nv_bfloat16* __restrict__ Ql,
    const __nv_bfloat16* __restrict__ Kh, const __nv_bfloat16* __restrict__ Kl,
    const __nv_bfloat16* __restrict__ Vth, const __nv_bfloat16* __restrict__ Vtl,
    __nv_bfloat16* __restrict__ Oh, __nv_bfloat16* __restrict__ Ol)
{
    extern __shared__ __nv_bfloat16 sm[];
    __nv_bfloat16* sQh = sm;
    __nv_bfloat16* sQl = sQh + 64 * QP2;
    __nv_bfloat16* sKh = sQl + 64 * QP2;
    __nv_bfloat16* sKl = sKh + 32 * QP2;
    __nv_bfloat16* sVh = sKl + 32 * QP2;
    __nv_bfloat16* sVl = sVh + 128 * VP2;

    const int tid = threadIdx.x, lane = tid & 31, w = tid >> 5;
    const int qt = (int)(gridDim.x - 1) - (int)blockIdx.x;  // longest tiles first
    const int h = blockIdx.y, b = blockIdx.z;
    const int kvh = h >> 2;
    const int vz = b * NKVHEADS + kvh;
    const unsigned bQh = smem_u32(sQh), bQl = smem_u32(sQl);
    const unsigned bKh = smem_u32(sKh), bKl = smem_u32(sKl);
    const unsigned bVh = smem_u32(sVh), bVl = smem_u32(sVl);
    const float L = 0.08838834764831845f * 1.4426950408889634f;

    // Load Q tile: 64 rows x 128 bf16 = 1024 uint4 (16 per row), 128 threads
#pragma unroll
    for (int l = 0; l < 8; l++) {
        int f = tid + l * 128;
        int row = f >> 4, dc = (f & 15) * 8;
        size_t go = (size_t)(b * SEQ + qt * 64 + row) * HIDDEN + h * 128 + dc;
        *(uint4*)&sQh[row * QP2 + dc] = *(const uint4*)(Qh + go);
        *(uint4*)&sQl[row * QP2 + dc] = *(const uint4*)(Ql + go);
    }

    float O[16][4];
#pragma unroll
    for (int i = 0; i < 16; i++)
#pragma unroll
        for (int v = 0; v < 4; v++) O[i][v] = 0.f;
    float m0 = -1e30f, m1 = -1e30f, l0 = 0.f, l1 = 0.f;

    const int nkv = (qt + 1) * 64;
    const int wrow = qt * 64 + w * 16;

    for (int kv0 = 0; kv0 < nkv; kv0 += 32) {
        __syncthreads();
        // K tile: 32 rows x 128 bf16 = 512 uint4
#pragma unroll
        for (int l = 0; l < 4; l++) {
            int f = tid + l * 128;
            int row = f >> 4, dc = (f & 15) * 8;
            size_t go = (size_t)(b * SEQ + kv0 + row) * KVDIM + kvh * 128 + dc;
            *(uint4*)&sKh[row * QP2 + dc] = *(const uint4*)(Kh + go);
            *(uint4*)&sKl[row * QP2 + dc] = *(const uint4*)(Kl + go);
        }
        // Vt tile: 128 d-rows x 32 kv = 512 uint4 (4 per row)
#pragma unroll
        for (int l = 0; l < 4; l++) {
            int f = tid + l * 128;
            int row = f >> 2, c = (f & 3) * 8;
            size_t go = (size_t)(vz * 128 + row) * SEQ + kv0 + c;
            *(uint4*)&sVh[row * VP2 + c] = *(const uint4*)(Vth + go);
            *(uint4*)&sVl[row * VP2 + c] = *(const uint4*)(Vtl + go);
        }
        __syncthreads();

        // S = Q K^T (m16 x n32, k=128), 3-term split
        float S[4][4];
#pragma unroll
        for (int i = 0; i < 4; i++)
#pragma unroll
            for (int v = 0; v < 4; v++) S[i][v] = 0.f;
#pragma unroll
        for (int kc = 0; kc < 8; kc++) {
            unsigned qh[4], ql[4];
            ldsm4(qh[0], qh[1], qh[2], qh[3], addrA(bQh, lane, w * 16, kc * 16, QP2));
            ldsm4(ql[0], ql[1], ql[2], ql[3], addrA(bQl, lane, w * 16, kc * 16, QP2));
#pragma unroll
            for (int nn = 0; nn < 2; nn++) {
                unsigned kh[4], kl[4];
                ldsm4(kh[0], kh[1], kh[2], kh[3], addrB(bKh, lane, nn * 16, kc * 16, QP2));
                ldsm4(kl[0], kl[1], kl[2], kl[3], addrB(bKl, lane, nn * 16, kc * 16, QP2));
                mma_bf16(S[nn * 2], qh, kh[0], kh[1]);
                mma_bf16(S[nn * 2], qh, kl[0], kl[1]);
                mma_bf16(S[nn * 2], ql, kh[0], kh[1]);
                mma_bf16(S[nn * 2 + 1], qh, kh[2], kh[3]);
                mma_bf16(S[nn * 2 + 1], qh, kl[2], kl[3]);
                mma_bf16(S[nn * 2 + 1], ql, kh[2], kh[3]);
            }
        }

        // Causal mask (diagonal tiles only)
        const int r0g = wrow + (lane >> 2);
        const int r1g = r0g + 8;
        if (kv0 + 31 > wrow) {
#pragma unroll
            for (int nf = 0; nf < 4; nf++) {
                int c = kv0 + nf * 8 + (lane & 3) * 2;
                if (c > r0g) S[nf][0] = -1e30f;
                if (c + 1 > r0g) S[nf][1] = -1e30f;
                if (c > r1g) S[nf][2] = -1e30f;
                if (c + 1 > r1g) S[nf][3] = -1e30f;
            }
        }

        // Online softmax
        float t0 = -1e30f, t1 = -1e30f;
#pragma unroll
        for (int nf = 0; nf < 4; nf++) {
            t0 = fmaxf(t0, fmaxf(S[nf][0], S[nf][1]));
            t1 = fmaxf(t1, fmaxf(S[nf][2], S[nf][3]));
        }
        t0 = fmaxf(t0, __shfl_xor_sync(0xffffffffu, t0, 1));
        t0 = fmaxf(t0, __shfl_xor_sync(0xffffffffu, t0, 2));
        t1 = fmaxf(t1, __shfl_xor_sync(0xffffffffu, t1, 1));
        t1 = fmaxf(t1, __shfl_xor_sync(0xffffffffu, t1, 2));
        float mn0 = fmaxf(m0, t0), mn1 = fmaxf(m1, t1);
        float c0 = ex2f((m0 - mn0) * L), c1 = ex2f((m1 - mn1) * L);
        m0 = mn0; m1 = mn1;
        float rs0 = 0.f, rs1 = 0.f;
#pragma unroll
        for (int nf = 0; nf < 4; nf++) {
            S[nf][0] = ex2f((S[nf][0] - mn0) * L);
            S[nf][1] = ex2f((S[nf][1] - mn0) * L);
            S[nf][2] = ex2f((S[nf][2] - mn1) * L);
            S[nf][3] = ex2f((S[nf][3] - mn1) * L);
            rs0 += S[nf][0] + S[nf][1];
            rs1 += S[nf][2] + S[nf][3];
        }
        rs0 += __shfl_xor_sync(0xffffffffu, rs0, 1);
        rs0 += __shfl_xor_sync(0xffffffffu, rs0, 2);
        rs1 += __shfl_xor_sync(0xffffffffu, rs1, 1);
        rs1 += __shfl_xor_sync(0xffffffffu, rs1, 2);
        l0 = l0 * c0 + rs0;
        l1 = l1 * c1 + rs1;
#pragma unroll
        for (int i = 0; i < 16; i++) {
            O[i][0] *= c0; O[i][1] *= c0; O[i][2] *= c1; O[i][3] *= c1;
        }

        // O += P V  (P hi/lo from S regs; V hi/lo from smem Vt)
#pragma unroll
        for (int kc = 0; kc < 2; kc++) {
            unsigned ah[4], al[4];
#pragma unroll
            for (int g = 0; g < 2; g++) {
                const float* s4 = S[kc * 2 + g];
                __nv_bfloat16 h0, l0b, h1, l1b, h2, l2b, h3, l3b;
                split_bf16(s4[0], h0, l0b); split_bf16(s4[1], h1, l1b);
                split_bf16(s4[2], h2, l2b); split_bf16(s4[3], h3, l3b);
                ah[g * 2]     = pack2(h0, h1); al[g * 2]     = pack2(l0b, l1b);
                ah[g * 2 + 1] = pack2(h2, h3); al[g * 2 + 1] = pack2(l2b, l3b);
            }
#pragma unroll
            for (int dn = 0; dn < 8; dn++) {
                unsigned vh[4], vl[4];
                ldsm4(vh[0], vh[1], vh[2], vh[3], addrB(bVh, lane, dn * 16, kc * 16, VP2));
                ldsm4(vl[0], vl[1], vl[2], vl[3], addrB(bVl, lane, dn * 16, kc * 16, VP2));
                mma_bf16(O[dn * 2], ah, vh[0], vh[1]);
                mma_bf16(O[dn * 2], ah, vl[0], vl[1]);
                mma_bf16(O[dn * 2], al, vh[0], vh[1]);
                mma_bf16(O[dn * 2 + 1], ah, vh[2], vh[3]);
                mma_bf16(O[dn * 2 + 1], ah, vl[2], vl[3]);
                mma_bf16(O[dn * 2 + 1], al, vh[2], vh[3]);
            }
        }
    }

    // Epilogue: write bf16 hi/lo splits directly
    float i0 = 1.f / l0, i1 = 1.f / l1;
    const int row0 = b * SEQ + wrow + (lane >> 2);
#pragma unroll
    for (int nf = 0; nf < 16; nf++) {
        int c = h * 128 + nf * 8 + (lane & 3) * 2;
        float a0 = O[nf][0] * i0, a1 = O[nf][1] * i0;
        float a2 = O[nf][2] * i1, a3 = O[nf][3] * i1;
        __nv_bfloat16 h0, l0b, h1, l1b, h2, l2b, h3, l3b;
        split_bf16(a0, h0, l0b); split_bf16(a1, h1, l1b);
        split_bf16(a2, h2, l2b); split_bf16(a3, h3, l3b);
        *(unsigned*)&Oh[(size_t)row0 * HIDDEN + c] = pack2(h0, h1);
        *(unsigned*)&Ol[(size_t)row0 * HIDDEN + c] = pack2(l0b, l1b);
        *(unsigned*)&Oh[(size_t)(row0 + 8) * HIDDEN + c] = pack2(h2, h3);
        *(unsigned*)&Ol[(size_t)(row0 + 8) * HIDDEN + c] = pack2(l2b, l3b);
    }
}

// ---------------------------------------------------------------------------
// Launch
// ---------------------------------------------------------------------------
extern "C" void kernel_launch(void* const* d_in, const int* in_sizes, int n_in,
                              void* d_out, int out_size)
{
    const float* hidden = (const float*)d_in[0];
    const int*   posids = (const int*)d_in[1];
    const float* Wq = (const float*)d_in[2];
    const float* bq = (const float*)d_in[3];
    const float* Wk = (const float*)d_in[4];
    const float* bk = (const float*)d_in[5];
    const float* Wv = (const float*)d_in[6];
    const float* bv = (const float*)d_in[7];
    const float* Wo = (const float*)d_in[8];
    const float* bo = (const float*)d_in[9];
    float* out = (float*)d_out;

    __nv_bfloat16 *Hh, *Hl, *Wqh, *Wql, *Wkh, *Wkl, *Wvh, *Wvl, *Woh, *Wol, *Ah, *Al;
    __nv_bfloat16 *Qh, *Ql, *Kh, *Kl, *Vth, *Vtl;
    float *qf, *kf, *vf;
    cudaGetSymbolAddress((void**)&Hh, g_Hh);   cudaGetSymbolAddress((void**)&Hl, g_Hl);
    cudaGetSymbolAddress((void**)&Wqh, g_Wqt_h); cudaGetSymbolAddress((void**)&Wql, g_Wqt_l);
    cudaGetSymbolAddress((void**)&Wkh, g_Wkt_h); cudaGetSymbolAddress((void**)&Wkl, g_Wkt_l);
    cudaGetSymbolAddress((void**)&Wvh, g_Wvt_h); cudaGetSymbolAddress((void**)&Wvl, g_Wvt_l);
    cudaGetSymbolAddress((void**)&Woh, g_Wot_h); cudaGetSymbolAddress((void**)&Wol, g_Wot_l);
    cudaGetSymbolAddress((void**)&Ah, g_Ah);   cudaGetSymbolAddress((void**)&Al, g_Al);
    cudaGetSymbolAddress((void**)&Qh, g_Qh);   cudaGetSymbolAddress((void**)&Ql, g_Ql);
    cudaGetSymbolAddress((void**)&Kh, g_Kh);   cudaGetSymbolAddress((void**)&Kl, g_Kl);
    cudaGetSymbolAddress((void**)&Vth, g_Vth); cudaGetSymbolAddress((void**)&Vtl, g_Vtl);
    cudaGetSymbolAddress((void**)&qf, g_qf);   cudaGetSymbolAddress((void**)&kf, g_kf);
    cudaGetSymbolAddress((void**)&vf, g_vf);

    // idx 0: split hidden
    split_f32<<<(MROWS * HIDDEN / 4 + 255) / 256, 256>>>(hidden, Hh, Hl, MROWS * HIDDEN / 4);
    // idx 1: all weight transposes in one launch
    transpose_all<<<dim3(HIDDEN / 32, HIDDEN / 32, 4), dim3(32, 8)>>>(
        Wq, Wk, Wv, Wo, Wqh, Wql, Wkh, Wkl, Wvh, Wvl, Woh, Wol);

    // idx 2: merged Q/K/V projection (wave-packed)
    cudaFuncSetAttribute(gemm_qkv, cudaFuncAttributeMaxDynamicSharedMemorySize, GEMM_SMEM);
    cudaFuncSetAttribute(gemm_bf16x3, cudaFuncAttributeMaxDynamicSharedMemorySize, GEMM_SMEM);
    gemm_qkv<<<dim3(24, MROWS / 128), 256, GEMM_SMEM>>>(
        Hh, Hl, Wqh, Wql, Wkh, Wkl, Wvh, Wvl, bq, bk, bv, qf, kf, vf);

    // idx 3: fused RoPE + split ; idx 4: V transpose + split
    rope_split<<<MROWS, 128>>>(posids, qf, kf, Qh, Ql, Kh, Kl);
    vt_split<<<dim3(SEQ / 32, HEADDIM / 32, BATCH * NKVHEADS), dim3(32, 8)>>>(vf, Vth, Vtl);

    // idx 5: attention (64 q-rows/CTA, 3 CTAs/SM)
    cudaFuncSetAttribute(attn_mma, cudaFuncAttributeMaxDynamicSharedMemorySize, ATTN_SMEM);
    attn_mma<<<dim3(SEQ / 64, NHEADS, BATCH), 128, ATTN_SMEM>>>(Qh, Ql, Kh, Kl, Vth, Vtl, Ah, Al);

    // idx 6: output projection
    gemm_bf16x3<<<dim3(HIDDEN / 128, MROWS / 128), 256, GEMM_SMEM>>>(Ah, Al, Woh, Wol, bo, out, MROWS, HIDDEN, HIDDEN);
}

// round 14
// speedup vs baseline: 1.0470x; 1.0470x over previous
#include <cuda_runtime.h>
#include <cuda_bf16.h>
#include <math.h>
#include <stdint.h>

#define HIDDEN   2048
#define NHEADS   16
#define NKVHEADS 4
#define HEADDIM  128
#define BATCH    2
#define SEQ      2048
#define MROWS    (BATCH * SEQ)          // 4096
#define KVDIM    (NKVHEADS * HEADDIM)   // 512

#define DEVINL __device__ __forceinline__

// ---------------------------------------------------------------------------
// Scratch
// ---------------------------------------------------------------------------
__device__ __nv_bfloat16 g_Hh[MROWS * HIDDEN], g_Hl[MROWS * HIDDEN];
__device__ __nv_bfloat16 g_Wqt_h[HIDDEN * HIDDEN], g_Wqt_l[HIDDEN * HIDDEN];
__device__ __nv_bfloat16 g_Wkt_h[KVDIM * HIDDEN],  g_Wkt_l[KVDIM * HIDDEN];
__device__ __nv_bfloat16 g_Wvt_h[KVDIM * HIDDEN],  g_Wvt_l[KVDIM * HIDDEN];
__device__ __nv_bfloat16 g_Wot_h[HIDDEN * HIDDEN], g_Wot_l[HIDDEN * HIDDEN];
__device__ float g_qf[MROWS * HIDDEN];
__device__ float g_kf[MROWS * KVDIM];
__device__ float g_vf[MROWS * KVDIM];
__device__ __nv_bfloat16 g_Ah[MROWS * HIDDEN], g_Al[MROWS * HIDDEN];
__device__ __nv_bfloat16 g_Qh[MROWS * HIDDEN], g_Ql[MROWS * HIDDEN];
__device__ __nv_bfloat16 g_Kh[MROWS * KVDIM],  g_Kl[MROWS * KVDIM];
__device__ __nv_bfloat16 g_Vth[BATCH * KVDIM * SEQ], g_Vtl[BATCH * KVDIM * SEQ]; // [z*128+d][s]

// ---------------------------------------------------------------------------
// PTX helpers
// ---------------------------------------------------------------------------
DEVINL unsigned smem_u32(const void* p) { return (unsigned)__cvta_generic_to_shared(p); }

DEVINL void ldsm4(unsigned& r0, unsigned& r1, unsigned& r2, unsigned& r3, unsigned a) {
    asm volatile("ldmatrix.sync.aligned.m8n8.x4.shared.b16 {%0,%1,%2,%3}, [%4];\n"
                 : "=r"(r0), "=r"(r1), "=r"(r2), "=r"(r3) : "r"(a));
}
DEVINL void mma_bf16(float c[4], const unsigned a[4], unsigned b0, unsigned b1) {
    asm volatile(
        "mma.sync.aligned.m16n8k16.row.col.f32.bf16.bf16.f32 "
        "{%0,%1,%2,%3}, {%4,%5,%6,%7}, {%8,%9}, {%0,%1,%2,%3};\n"
        : "+f"(c[0]), "+f"(c[1]), "+f"(c[2]), "+f"(c[3])
        : "r"(a[0]), "r"(a[1]), "r"(a[2]), "r"(a[3]), "r"(b0), "r"(b1));
}
DEVINL unsigned addrA(unsigned base, int lane, int row0, int col0, int pitch) {
    int r = row0 + (lane & 15);
    int c = col0 + ((lane >> 4) << 3);
    return base + (unsigned)(r * pitch + c) * 2u;
}
DEVINL unsigned addrB(unsigned base, int lane, int row0, int col0, int pitch) {
    int r = row0 + ((lane >> 4) << 3) + (lane & 7);
    int c = col0 + (((lane >> 3) & 1) << 3);
    return base + (unsigned)(r * pitch + c) * 2u;
}
DEVINL float ex2f(float x) { float r; asm("ex2.approx.ftz.f32 %0, %1;" : "=f"(r) : "f"(x)); return r; }

DEVINL void cpasync16(unsigned dst, const void* src) {
    asm volatile("cp.async.cg.shared.global [%0], [%1], 16;\n" :: "r"(dst), "l"(src));
}
DEVINL void cp_commit() { asm volatile("cp.async.commit_group;\n" ::); }
DEVINL void cp_wait0()  { asm volatile("cp.async.wait_group 0;\n" ::); }
DEVINL void cp_wait1()  { asm volatile("cp.async.wait_group 1;\n" ::); }

DEVINL void split_bf16(float x, __nv_bfloat16& h, __nv_bfloat16& l) {
    h = __float2bfloat16(x);
    l = __float2bfloat16(x - __bfloat162float(h));
}
DEVINL unsigned pack2(__nv_bfloat16 lo, __nv_bfloat16 hi) {
    return (unsigned)__bfloat16_as_ushort(lo) | ((unsigned)__bfloat16_as_ushort(hi) << 16);
}

// ---------------------------------------------------------------------------
// fp32 -> bf16 hi/lo split (hidden activations)
// ---------------------------------------------------------------------------
__global__ void split_f32(const float* __restrict__ X,
                          __nv_bfloat16* __restrict__ H,
                          __nv_bfloat16* __restrict__ L, int n4)
{
    int i = blockIdx.x * blockDim.x + threadIdx.x;
    if (i >= n4) return;
    float4 v = ((const float4*)X)[i];
    __nv_bfloat16 h0, h1, h2, h3, l0, l1, l2, l3;
    split_bf16(v.x, h0, l0); split_bf16(v.y, h1, l1);
    split_bf16(v.z, h2, l2); split_bf16(v.w, h3, l3);
    *(uint2*)(H + (size_t)i * 4) = make_uint2(pack2(h0, h1), pack2(h2, h3));
    *(uint2*)(L + (size_t)i * 4) = make_uint2(pack2(l0, l1), pack2(l2, l3));
}

// ---------------------------------------------------------------------------
// All four W [K][N] fp32 -> [N][K] bf16 hi/lo in ONE launch (grid.z selects)
// ---------------------------------------------------------------------------
__global__ void transpose_all(
    const float* __restrict__ Wq, const float* __restrict__ Wk,
    const float* __restrict__ Wv, const float* __restrict__ Wo,
    __nv_bfloat16* __restrict__ Wqh, __nv_bfloat16* __restrict__ Wql,
    __nv_bfloat16* __restrict__ Wkh, __nv_bfloat16* __restrict__ Wkl,
    __nv_bfloat16* __restrict__ Wvh, __nv_bfloat16* __restrict__ Wvl,
    __nv_bfloat16* __restrict__ Woh, __nv_bfloat16* __restrict__ Wol)
{
    const int z = blockIdx.z;
    const float* W; __nv_bfloat16 *Th, *Tl; int N;
    if (z == 0)      { W = Wq; Th = Wqh; Tl = Wql; N = HIDDEN; }
    else if (z == 1) { W = Wk; Th = Wkh; Tl = Wkl; N = KVDIM; }
    else if (z == 2) { W = Wv; Th = Wvh; Tl = Wvl; N = KVDIM; }
    else             { W = Wo; Th = Woh; Tl = Wol; N = HIDDEN; }

    int n0 = blockIdx.x * 32, k0 = blockIdx.y * 32;
    if (n0 >= N) return;

    __shared__ float t[32][33];
    int tx = threadIdx.x, ty = threadIdx.y;
#pragma unroll
    for (int i = 0; i < 4; i++)
        t[ty + i * 8][tx] = W[(size_t)(k0 + ty + i * 8) * N + n0 + tx];
    __syncthreads();
#pragma unroll
    for (int i = 0; i < 4; i++) {
        float v = t[tx][ty + i * 8];
        __nv_bfloat16 h, l;
        split_bf16(v, h, l);
        size_t o = (size_t)(n0 + ty + i * 8) * HIDDEN + k0 + tx;
        Th[o] = h; Tl[o] = l;
    }
}

// V [b*S+s][kvh*128+d] fp32 -> Vt [(b*4+kvh)*128+d][s] bf16 hi/lo
__global__ void vt_split(const float* __restrict__ vf,
                         __nv_bfloat16* __restrict__ Th,
                         __nv_bfloat16* __restrict__ Tl)
{
    __shared__ float t[32][33];
    int s0 = blockIdx.x * 32, d0 = blockIdx.y * 32, z = blockIdx.z;
    int b = z >> 2, kvh = z & 3;
    int tx = threadIdx.x, ty = threadIdx.y;
#pragma unroll
    for (int i = 0; i < 4; i++)
        t[ty + i * 8][tx] = vf[(size_t)(b * SEQ + s0 + ty + i * 8) * KVDIM + kvh * 128 + d0 + tx];
    __syncthreads();
#pragma unroll
    for (int i = 0; i < 4; i++) {
        float v = t[tx][ty + i * 8];
        __nv_bfloat16 h, l;
        split_bf16(v, h, l);
        size_t o = (size_t)(z * 128 + d0 + ty + i * 8) * SEQ + s0 + tx;
        Th[o] = h; Tl[o] = l;
    }
}

// ---------------------------------------------------------------------------
// GEMM core (validated): one 128x128 tile of C = (Ah+Al)@(Bh+Bl)^T + bias
// ---------------------------------------------------------------------------
#define KP 40
#define GEMM_TILE_B  (128 * KP * 2)
#define GEMM_STAGE_B (4 * GEMM_TILE_B)
#define GEMM_SMEM    (2 * GEMM_STAGE_B)          // 81920

DEVINL void gemm_tile(
    const __nv_bfloat16* Ah, const __nv_bfloat16* Al,
    const __nv_bfloat16* Bh, const __nv_bfloat16* Bl,
    const float* bias, float* C,
    int m0, int n0loc, int N, int K, char* gsm)
{
    const unsigned sbase = smem_u32(gsm);
    const int tid = threadIdx.x, lane = tid & 31, warp = tid >> 5;
    const int wm = warp >> 2, wn = warp & 3;

    float acc[4][4][4];
#pragma unroll
    for (int i = 0; i < 4; i++)
#pragma unroll
        for (int j = 0; j < 4; j++)
#pragma unroll
            for (int v = 0; v < 4; v++) acc[i][j][v] = 0.f;

    const int nk = K / 32;

    auto issue = [&](int st, int k0) {
        unsigned sb = sbase + (unsigned)st * GEMM_STAGE_B;
#pragma unroll
        for (int l = 0; l < 2; l++) {
            int f = tid + l * 256;
            int row = f >> 2;
            int kc = (f & 3) * 8;
            unsigned so = (unsigned)(row * KP + kc) * 2u;
            size_t goA = (size_t)(m0 + row) * K + k0 + kc;
            size_t goB = (size_t)(n0loc + row) * K + k0 + kc;
            cpasync16(sb + so,                     Ah + goA);
            cpasync16(sb + GEMM_TILE_B + so,       Al + goA);
            cpasync16(sb + 2 * GEMM_TILE_B + so,   Bh + goB);
            cpasync16(sb + 3 * GEMM_TILE_B + so,   Bl + goB);
        }
    };

    issue(0, 0);
    cp_commit();

    for (int kt = 0; kt < nk; kt++) {
        int st = kt & 1;
        if (kt + 1 < nk) { issue(st ^ 1, (kt + 1) * 32); cp_commit(); cp_wait1(); }
        else             { cp_wait0(); }
        __syncthreads();

        unsigned sb  = sbase + (unsigned)st * GEMM_STAGE_B;
        unsigned bAh = sb;
        unsigned bAl = sb + GEMM_TILE_B;
        unsigned bBh = sb + 2 * GEMM_TILE_B;
        unsigned bBl = sb + 3 * GEMM_TILE_B;

#pragma unroll
        for (int ks = 0; ks < 2; ks++) {
            int kb = ks * 16;
            unsigned bh[4][2], bl[4][2];
#pragma unroll
            for (int g = 0; g < 2; g++) {
                unsigned r0, r1, r2, r3;
                ldsm4(r0, r1, r2, r3, addrB(bBh, lane, wn * 32 + g * 16, kb, KP));
                bh[g * 2][0] = r0; bh[g * 2][1] = r1;
                bh[g * 2 + 1][0] = r2; bh[g * 2 + 1][1] = r3;
                ldsm4(r0, r1, r2, r3, addrB(bBl, lane, wn * 32 + g * 16, kb, KP));
                bl[g * 2][0] = r0; bl[g * 2][1] = r1;
                bl[g * 2 + 1][0] = r2; bl[g * 2 + 1][1] = r3;
            }
#pragma unroll
            for (int mf = 0; mf < 4; mf++) {
                unsigned ah[4], al[4];
                ldsm4(ah[0], ah[1], ah[2], ah[3], addrA(bAh, lane, wm * 64 + mf * 16, kb, KP));
                ldsm4(al[0], al[1], al[2], al[3], addrA(bAl, lane, wm * 64 + mf * 16, kb, KP));
#pragma unroll
                for (int nf = 0; nf < 4; nf++) {
                    mma_bf16(acc[mf][nf], ah, bh[nf][0], bh[nf][1]);
                    mma_bf16(acc[mf][nf], ah, bl[nf][0], bl[nf][1]);
                    mma_bf16(acc[mf][nf], al, bh[nf][0], bh[nf][1]);
                }
            }
        }
        __syncthreads();
    }

    const int rb = m0 + wm * 64, cb = n0loc + wn * 32;
#pragma unroll
    for (int mf = 0; mf < 4; mf++)
#pragma unroll
        for (int nf = 0; nf < 4; nf++) {
            int r = rb + mf * 16 + (lane >> 2);
            int c = cb + nf * 8 + (lane & 3) * 2;
            float b0 = bias[c], b1 = bias[c + 1];
            *(float2*)&C[(size_t)r * N + c] =
                make_float2(acc[mf][nf][0] + b0, acc[mf][nf][1] + b1);
            *(float2*)&C[(size_t)(r + 8) * N + c] =
                make_float2(acc[mf][nf][2] + b0, acc[mf][nf][3] + b1);
        }
}

// Merged Q/K/V projection: one launch, grid (24, 32).
__global__ __launch_bounds__(256) void gemm_qkv(
    const __nv_bfloat16* __restrict__ Ah, const __nv_bfloat16* __restrict__ Al,
    const __nv_bfloat16* __restrict__ Wqh, const __nv_bfloat16* __restrict__ Wql,
    const __nv_bfloat16* __restrict__ Wkh, const __nv_bfloat16* __restrict__ Wkl,
    const __nv_bfloat16* __restrict__ Wvh, const __nv_bfloat16* __restrict__ Wvl,
    const float* __restrict__ bq, const float* __restrict__ bk, const float* __restrict__ bv,
    float* __restrict__ qf, float* __restrict__ kf, float* __restrict__ vf)
{
    extern __shared__ char gsm[];
    const int nt = blockIdx.x;
    const int m0 = blockIdx.y * 128;
    const __nv_bfloat16 *Bh, *Bl; const float* bias; float* C; int N, n0;
    if (nt < 16)      { Bh = Wqh; Bl = Wql; bias = bq; C = qf; N = HIDDEN; n0 = nt * 128; }
    else if (nt < 20) { Bh = Wkh; Bl = Wkl; bias = bk; C = kf; N = KVDIM;  n0 = (nt - 16) * 128; }
    else              { Bh = Wvh; Bl = Wvl; bias = bv; C = vf; N = KVDIM;  n0 = (nt - 20) * 128; }
    gemm_tile(Ah, Al, Bh, Bl, bias, C, m0, n0, N, HIDDEN, gsm);
}

__global__ __launch_bounds__(256) void gemm_bf16x3(
    const __nv_bfloat16* __restrict__ Ah, const __nv_bfloat16* __restrict__ Al,
    const __nv_bfloat16* __restrict__ Bh, const __nv_bfloat16* __restrict__ Bl,
    const float* __restrict__ bias, float* __restrict__ C,
    int M, int N, int K)
{
    extern __shared__ char gsm[];
    gemm_tile(Ah, Al, Bh, Bl, bias, C, blockIdx.y * 128, blockIdx.x * 128, N, K, gsm);
}

// ---------------------------------------------------------------------------
// RoPE on Q, K fp32 -> bf16 hi/lo splits (fused).
// Processes d-PAIRS: float2 loads, packed 4-byte stores (store-issue fix).
// ---------------------------------------------------------------------------
__global__ __launch_bounds__(128) void rope_split(
    const int* __restrict__ pos_ids,
    const float* __restrict__ qf, const float* __restrict__ kf,
    __nv_bfloat16* __restrict__ Qh, __nv_bfloat16* __restrict__ Ql,
    __nv_bfloat16* __restrict__ Kh, __nv_bfloat16* __restrict__ Kl)
{
    const int bs = blockIdx.x;
    const int t = threadIdx.x;
    __shared__ float cs[64], sn[64];
    if (t < 64) {
        double pos = (double)pos_ids[bs];
        double inv = exp(-((double)t / 64.0) * 13.815510557964274);
        double fr = pos * inv;
        cs[t] = (float)cos(fr);
        sn[t] = (float)sin(fr);
    }
    __syncthreads();

    // Q: 16 heads x 32 d-pairs = 512 pair-tasks; 128 threads x 4 iters
    const float* q = qf + (size_t)bs * HIDDEN;
#pragma unroll
    for (int p = t; p < NHEADS * 32; p += 128) {
        int h = p >> 5, d = (p & 31) * 2;
        size_t base = (size_t)bs * HIDDEN + h * HEADDIM;
        float2 x0 = *(const float2*)(q + h * HEADDIM + d);
        float2 x1 = *(const float2*)(q + h * HEADDIM + d + 64);
        float c0 = cs[d], c1 = cs[d + 1], s0 = sn[d], s1 = sn[d + 1];
        float ya0 = x0.x * c0 - x1.x * s0, ya1 = x0.y * c1 - x1.y * s1;
        float yb0 = x1.x * c0 + x0.x * s0, yb1 = x1.y * c1 + x0.y * s1;
        __nv_bfloat16 ha0, la0, ha1, la1, hb0, lb0, hb1, lb1;
        split_bf16(ya0, ha0, la0); split_bf16(ya1, ha1, la1);
        split_bf16(yb0, hb0, lb0); split_bf16(yb1, hb1, lb1);
        *(unsigned*)&Qh[base + d]      = pack2(ha0, ha1);
        *(unsigned*)&Ql[base + d]      = pack2(la0, la1);
        *(unsigned*)&Qh[base + d + 64] = pack2(hb0, hb1);
        *(unsigned*)&Ql[base + d + 64] = pack2(lb0, lb1);
    }
    // K: 4 heads x 32 d-pairs = 128 pair-tasks; 1 iter
    const float* k = kf + (size_t)bs * KVDIM;
#pragma unroll
    for (int p = t; p < NKVHEADS * 32; p += 128) {
        int h = p >> 5, d = (p & 31) * 2;
        size_t base = (size_t)bs * KVDIM + h * HEADDIM;
        float2 x0 = *(const float2*)(k + h * HEADDIM + d);
        float2 x1 = *(const float2*)(k + h * HEADDIM + d + 64);
        float c0 = cs[d], c1 = cs[d + 1], s0 = sn[d], s1 = sn[d + 1];
        float ya0 = x0.x * c0 - x1.x * s0, ya1 = x0.y * c1 - x1.y * s1;
        float yb0 = x1.x * c0 + x0.x * s0, yb1 = x1.y * c1 + x0.y * s1;
        __nv_bfloat16 ha0, la0, ha1, la1, hb0, lb0, hb1, lb1;
        split_bf16(ya0, ha0, la0); split_bf16(ya1, ha1, la1);
        split_bf16(yb0, hb0, lb0); split_bf16(yb1, hb1, lb1);
        *(unsigned*)&Kh[base + d]      = pack2(ha0, ha1);
        *(unsigned*)&Kl[base + d]      = pack2(la0, la1);
        *(unsigned*)&Kh[base + d + 64] = pack2(hb0, hb1);
        *(unsigned*)&Kl[base + d + 64] = pack2(lb0, lb1);
    }
}

// ---------------------------------------------------------------------------
// Tensor-core causal flash attention (bf16x3), 2-stage cp.async K/V pipeline.
// Round-11 validated configuration: 256 thr, 128 q rows, KV tile 64, 213 KB.
// ---------------------------------------------------------------------------
#define QP2 136
#define VP2 72
#define AT_OQ  0u
#define AT_OQL 34816u
#define AT_OK  69632u
#define AT_KST 34816u
#define AT_OV  139264u
#define AT_VST 36864u
#define ATTN_SMEM 212992

__global__ __launch_bounds__(256) void attn_mma(
    const __nv_bfloat16* __restrict__ Qh, const __nv_bfloat16* __restrict__ Ql,
    const __nv_bfloat16* __restrict__ Kh, const __nv_bfloat16* __restrict__ Kl,
    const __nv_bfloat16* __restrict__ Vth, const __nv_bfloat16* __restrict__ Vtl,
    __nv_bfloat16* __restrict__ Oh, __nv_bfloat16* __restrict__ Ol)
{
    extern __shared__ __nv_bfloat16 sm[];
    const unsigned sbase = smem_u32(sm);

    const int tid = threadIdx.x, lane = tid & 31, w = tid >> 5;
    const int qt = blockIdx.x, h = blockIdx.y, b = blockIdx.z;
    const int kvh = h >> 2;
    const int vz = b * NKVHEADS + kvh;
    const float L = 0.08838834764831845f * 1.4426950408889634f;

    __nv_bfloat16* sQh = sm;
    __nv_bfloat16* sQl = sm + 128 * QP2;
#pragma unroll
    for (int l = 0; l < 8; l++) {
        int f = tid + l * 256;
        int row = f >> 4, dc = (f & 15) * 8;
        size_t go = (size_t)(b * SEQ + qt * 128 + row) * HIDDEN + h * 128 + dc;
        *(uint4*)&sQh[row * QP2 + dc] = *(const uint4*)(Qh + go);
        *(uint4*)&sQl[row * QP2 + dc] = *(const uint4*)(Ql + go);
    }

    auto issue_kv = [&](int st, int kv0) {
        unsigned kb = sbase + AT_OK + (unsigned)st * AT_KST;
        unsigned vb = sbase + AT_OV + (unsigned)st * AT_VST;
#pragma unroll
        for (int l = 0; l < 4; l++) {
            int f = tid + l * 256;
            int row = f >> 4, dc = (f & 15) * 8;
            unsigned so = (unsigned)(row * QP2 + dc) * 2u;
            size_t go = (size_t)(b * SEQ + kv0 + row) * KVDIM + kvh * 128 + dc;
            cpasync16(kb + so,          Kh + go);
            cpasync16(kb + 17408u + so, Kl + go);
        }
#pragma unroll
        for (int l = 0; l < 4; l++) {
            int f = tid + l * 256;
            int row = f >> 3, c = (f & 7) * 8;
            unsigned so = (unsigned)(row * VP2 + c) * 2u;
            size_t go = (size_t)(vz * 128 + row) * SEQ + kv0 + c;
            cpasync16(vb + so,          Vth + go);
            cpasync16(vb + 18432u + so, Vtl + go);
        }
    };

    float O[16][4];
#pragma unroll
    for (int i = 0; i < 16; i++)
#pragma unroll
        for (int v = 0; v < 4; v++) O[i][v] = 0.f;
    float m0 = -1e30f, m1 = -1e30f, l0 = 0.f, l1 = 0.f;

    const int nkv = (qt + 1) * 128;
    const int wrow = qt * 128 + w * 16;

    issue_kv(0, 0);
    cp_commit();

    for (int kv0 = 0, it = 0; kv0 < nkv; kv0 += 64, it ^= 1) {
        if (kv0 + 64 < nkv) { issue_kv(it ^ 1, kv0 + 64); cp_commit(); cp_wait1(); }
        else                { cp_wait0(); }
        __syncthreads();

        const unsigned bKh = sbase + AT_OK + (unsigned)it * AT_KST;
        const unsigned bKl = bKh + 17408u;
        const unsigned bVh = sbase + AT_OV + (unsigned)it * AT_VST;
        const unsigned bVl = bVh + 18432u;
        const unsigned bQh = sbase + AT_OQ;
        const unsigned bQl = sbase + AT_OQL;

        float S[8][4];
#pragma unroll
        for (int i = 0; i < 8; i++)
#pragma unroll
            for (int v = 0; v < 4; v++) S[i][v] = 0.f;
#pragma unroll
        for (int kc = 0; kc < 8; kc++) {
            unsigned qh[4], ql[4];
            ldsm4(qh[0], qh[1], qh[2], qh[3], addrA(bQh, lane, w * 16, kc * 16, QP2));
            ldsm4(ql[0], ql[1], ql[2], ql[3], addrA(bQl, lane, w * 16, kc * 16, QP2));
#pragma unroll
            for (int nn = 0; nn < 4; nn++) {
                unsigned kh[4], kl[4];
                ldsm4(kh[0], kh[1], kh[2], kh[3], addrB(bKh, lane, nn * 16, kc * 16, QP2));
                ldsm4(kl[0], kl[1], kl[2], kl[3], addrB(bKl, lane, nn * 16, kc * 16, QP2));
                mma_bf16(S[nn * 2], qh, kh[0], kh[1]);
                mma_bf16(S[nn * 2], qh, kl[0], kl[1]);
                mma_bf16(S[nn * 2], ql, kh[0], kh[1]);
                mma_bf16(S[nn * 2 + 1], qh, kh[2], kh[3]);
                mma_bf16(S[nn * 2 + 1], qh, kl[2], kl[3]);
                mma_bf16(S[nn * 2 + 1], ql, kh[2], kh[3]);
            }
        }

        const int r0g = wrow + (lane >> 2);
        const int r1g = r0g + 8;
        if (kv0 + 63 > wrow) {
#pragma unroll
            for (int nf = 0; nf < 8; nf++) {
                int c = kv0 + nf * 8 + (lane & 3) * 2;
                if (c > r0g) S[nf][0] = -1e30f;
                if (c + 1 > r0g) S[nf][1] = -1e30f;
                if (c > r1g) S[nf][2] = -1e30f;
                if (c + 1 > r1g) S[nf][3] = -1e30f;
            }
        }

        float t0 = -1e30f, t1 = -1e30f;
#pragma unroll
        for (int nf = 0; nf < 8; nf++) {
            t0 = fmaxf(t0, fmaxf(S[nf][0], S[nf][1]));
            t1 = fmaxf(t1, fmaxf(S[nf][2], S[nf][3]));
        }
        t0 = fmaxf(t0, __shfl_xor_sync(0xffffffffu, t0, 1));
        t0 = fmaxf(t0, __shfl_xor_sync(0xffffffffu, t0, 2));
        t1 = fmaxf(t1, __shfl_xor_sync(0xffffffffu, t1, 1));
        t1 = fmaxf(t1, __shfl_xor_sync(0xffffffffu, t1, 2));
        float mn0 = fmaxf(m0, t0), mn1 = fmaxf(m1, t1);
        float c0 = ex2f((m0 - mn0) * L), c1 = ex2f((m1 - mn1) * L);
        m0 = mn0; m1 = mn1;
        float rs0 = 0.f, rs1 = 0.f;
#pragma unroll
        for (int nf = 0; nf < 8; nf++) {
            S[nf][0] = ex2f((S[nf][0] - mn0) * L);
            S[nf][1] = ex2f((S[nf][1] - mn0) * L);
            S[nf][2] = ex2f((S[nf][2] - mn1) * L);
            S[nf][3] = ex2f((S[nf][3] - mn1) * L);
            rs0 += S[nf][0] + S[nf][1];
            rs1 += S[nf][2] + S[nf][3];
        }
        rs0 += __shfl_xor_sync(0xffffffffu, rs0, 1);
        rs0 += __shfl_xor_sync(0xffffffffu, rs0, 2);
        rs1 += __shfl_xor_sync(0xffffffffu, rs1, 1);
        rs1 += __shfl_xor_sync(0xffffffffu, rs1, 2);
        l0 = l0 * c0 + rs0;
        l1 = l1 * c1 + rs1;
#pragma unroll
        for (int i = 0; i < 16; i++) {
            O[i][0] *= c0; O[i][1] *= c0; O[i][2] *= c1; O[i][3] *= c1;
        }

#pragma unroll
        for (int kc = 0; kc < 4; kc++) {
            unsigned ah[4], al[4];
#pragma unroll
            for (int g = 0; g < 2; g++) {
                const float* s4 = S[kc * 2 + g];
                __nv_bfloat16 h0, l0b, h1, l1b, h2, l2b, h3, l3b;
                split_bf16(s4[0], h0, l0b); split_bf16(s4[1], h1, l1b);
                split_bf16(s4[2], h2, l2b); split_bf16(s4[3], h3, l3b);
                ah[g * 2]     = pack2(h0, h1); al[g * 2]     = pack2(l0b, l1b);
                ah[g * 2 + 1] = pack2(h2, h3); al[g * 2 + 1] = pack2(l2b, l3b);
            }
#pragma unroll
            for (int dn = 0; dn < 8; dn++) {
                unsigned vh[4], vl[4];
                ldsm4(vh[0], vh[1], vh[2], vh[3], addrB(bVh, lane, dn * 16, kc * 16, VP2));
                ldsm4(vl[0], vl[1], vl[2], vl[3], addrB(bVl, lane, dn * 16, kc * 16, VP2));
                mma_bf16(O[dn * 2], ah, vh[0], vh[1]);
                mma_bf16(O[dn * 2], ah, vl[0], vl[1]);
                mma_bf16(O[dn * 2], al, vh[0], vh[1]);
                mma_bf16(O[dn * 2 + 1], ah, vh[2], vh[3]);
                mma_bf16(O[dn * 2 + 1], ah, vl[2], vl[3]);
                mma_bf16(O[dn * 2 + 1], al, vh[2], vh[3]);
            }
        }
        __syncthreads();
    }

    float i0 = 1.f / l0, i1 = 1.f / l1;
    const int row0 = b * SEQ + wrow + (lane >> 2);
#pragma unroll
    for (int nf = 0; nf < 16; nf++) {
        int c = h * 128 + nf * 8 + (lane & 3) * 2;
        float a0 = O[nf][0] * i0, a1 = O[nf][1] * i0;
        float a2 = O[nf][2] * i1, a3 = O[nf][3] * i1;
        __nv_bfloat16 h0, l0b, h1, l1b, h2, l2b, h3, l3b;
        split_bf16(a0, h0, l0b); split_bf16(a1, h1, l1b);
        split_bf16(a2, h2, l2b); split_bf16(a3, h3, l3b);
        *(unsigned*)&Oh[(size_t)row0 * HIDDEN + c] = pack2(h0, h1);
        *(unsigned*)&Ol[(size_t)row0 * HIDDEN + c] = pack2(l0b, l1b);
        *(unsigned*)&Oh[(size_t)(row0 + 8) * HIDDEN + c] = pack2(h2, h3);
        *(unsigned*)&Ol[(size_t)(row0 + 8) * HIDDEN + c] = pack2(l2b, l3b);
    }
}

// ---------------------------------------------------------------------------
// Launch
// ---------------------------------------------------------------------------
extern "C" void kernel_launch(void* const* d_in, const int* in_sizes, int n_in,
                              void* d_out, int out_size)
{
    const float* hidden = (const float*)d_in[0];
    const int*   posids = (const int*)d_in[1];
    const float* Wq = (const float*)d_in[2];
    const float* bq = (const float*)d_in[3];
    const float* Wk = (const float*)d_in[4];
    const float* bk = (const float*)d_in[5];
    const float* Wv = (const float*)d_in[6];
    const float* bv = (const float*)d_in[7];
    const float* Wo = (const float*)d_in[8];
    const float* bo = (const float*)d_in[9];
    float* out = (float*)d_out;

    __nv_bfloat16 *Hh, *Hl, *Wqh, *Wql, *Wkh, *Wkl, *Wvh, *Wvl, *Woh, *Wol, *Ah, *Al;
    __nv_bfloat16 *Qh, *Ql, *Kh, *Kl, *Vth, *Vtl;
    float *qf, *kf, *vf;
    cudaGetSymbolAddress((void**)&Hh, g_Hh);   cudaGetSymbolAddress((void**)&Hl, g_Hl);
    cudaGetSymbolAddress((void**)&Wqh, g_Wqt_h); cudaGetSymbolAddress((void**)&Wql, g_Wqt_l);
    cudaGetSymbolAddress((void**)&Wkh, g_Wkt_h); cudaGetSymbolAddress((void**)&Wkl, g_Wkt_l);
    cudaGetSymbolAddress((void**)&Wvh, g_Wvt_h); cudaGetSymbolAddress((void**)&Wvl, g_Wvt_l);
    cudaGetSymbolAddress((void**)&Woh, g_Wot_h); cudaGetSymbolAddress((void**)&Wol, g_Wot_l);
    cudaGetSymbolAddress((void**)&Ah, g_Ah);   cudaGetSymbolAddress((void**)&Al, g_Al);
    cudaGetSymbolAddress((void**)&Qh, g_Qh);   cudaGetSymbolAddress((void**)&Ql, g_Ql);
    cudaGetSymbolAddress((void**)&Kh, g_Kh);   cudaGetSymbolAddress((void**)&Kl, g_Kl);
    cudaGetSymbolAddress((void**)&Vth, g_Vth); cudaGetSymbolAddress((void**)&Vtl, g_Vtl);
    cudaGetSymbolAddress((void**)&qf, g_qf);   cudaGetSymbolAddress((void**)&kf, g_kf);
    cudaGetSymbolAddress((void**)&vf, g_vf);

    // idx 0: split hidden
    split_f32<<<(MROWS * HIDDEN / 4 + 255) / 256, 256>>>(hidden, Hh, Hl, MROWS * HIDDEN / 4);
    // idx 1: all weight transposes in one launch
    transpose_all<<<dim3(HIDDEN / 32, HIDDEN / 32, 4), dim3(32, 8)>>>(
        Wq, Wk, Wv, Wo, Wqh, Wql, Wkh, Wkl, Wvh, Wvl, Woh, Wol);

    // idx 2: merged Q/K/V projection (wave-packed)
    cudaFuncSetAttribute(gemm_qkv, cudaFuncAttributeMaxDynamicSharedMemorySize, GEMM_SMEM);
    cudaFuncSetAttribute(gemm_bf16x3, cudaFuncAttributeMaxDynamicSharedMemorySize, GEMM_SMEM);
    gemm_qkv<<<dim3(24, MROWS / 128), 256, GEMM_SMEM>>>(
        Hh, Hl, Wqh, Wql, Wkh, Wkl, Wvh, Wvl, bq, bk, bv, qf, kf, vf);

    // idx 3: fused RoPE + split (vectorized stores) ; idx 4: V transpose + split
    rope_split<<<MROWS, 128>>>(posids, qf, kf, Qh, Ql, Kh, Kl);
    vt_split<<<dim3(SEQ / 32, HEADDIM / 32, BATCH * NKVHEADS), dim3(32, 8)>>>(vf, Vth, Vtl);

    // idx 5: attention (round-11 validated config)
    cudaFuncSetAttribute(attn_mma, cudaFuncAttributeMaxDynamicSharedMemorySize, ATTN_SMEM);
    attn_mma<<<dim3(SEQ / 128, NHEADS, BATCH), 256, ATTN_SMEM>>>(Qh, Ql, Kh, Kl, Vth, Vtl, Ah, Al);

    // idx 6: output projection
    gemm_bf16x3<<<dim3(HIDDEN / 128, MROWS / 128), 256, GEMM_SMEM>>>(Ah, Al, Woh, Wol, bo, out, MROWS, HIDDEN, HIDDEN);
}

// round 15
// speedup vs baseline: 1.1216x; 1.0713x over previous
#include <cuda_runtime.h>
#include <cuda_bf16.h>
#include <math.h>
#include <stdint.h>

#define HIDDEN   2048
#define NHEADS   16
#define NKVHEADS 4
#define HEADDIM  128
#define BATCH    2
#define SEQ      2048
#define MROWS    (BATCH * SEQ)          // 4096
#define KVDIM    (NKVHEADS * HEADDIM)   // 512

#define DEVINL __device__ __forceinline__

// ---------------------------------------------------------------------------
// Scratch
// ---------------------------------------------------------------------------
__device__ __nv_bfloat16 g_Hh[MROWS * HIDDEN], g_Hl[MROWS * HIDDEN];
__device__ __nv_bfloat16 g_Wqt_h[HIDDEN * HIDDEN], g_Wqt_l[HIDDEN * HIDDEN];
__device__ __nv_bfloat16 g_Wkt_h[KVDIM * HIDDEN],  g_Wkt_l[KVDIM * HIDDEN];
__device__ __nv_bfloat16 g_Wvt_h[KVDIM * HIDDEN],  g_Wvt_l[KVDIM * HIDDEN];
__device__ __nv_bfloat16 g_Wot_h[HIDDEN * HIDDEN], g_Wot_l[HIDDEN * HIDDEN];
__device__ float g_qf[MROWS * HIDDEN];
__device__ float g_kf[MROWS * KVDIM];
__device__ float g_vf[MROWS * KVDIM];
__device__ __nv_bfloat16 g_Ah[MROWS * HIDDEN], g_Al[MROWS * HIDDEN];
__device__ __nv_bfloat16 g_Qh[MROWS * HIDDEN], g_Ql[MROWS * HIDDEN];
__device__ __nv_bfloat16 g_Kh[MROWS * KVDIM],  g_Kl[MROWS * KVDIM];
__device__ __nv_bfloat16 g_Vth[BATCH * KVDIM * SEQ], g_Vtl[BATCH * KVDIM * SEQ]; // [z*128+d][s]

// ---------------------------------------------------------------------------
// PTX helpers
// ---------------------------------------------------------------------------
DEVINL unsigned smem_u32(const void* p) { return (unsigned)__cvta_generic_to_shared(p); }

DEVINL void ldsm4(unsigned& r0, unsigned& r1, unsigned& r2, unsigned& r3, unsigned a) {
    asm volatile("ldmatrix.sync.aligned.m8n8.x4.shared.b16 {%0,%1,%2,%3}, [%4];\n"
                 : "=r"(r0), "=r"(r1), "=r"(r2), "=r"(r3) : "r"(a));
}
DEVINL void mma_bf16(float c[4], const unsigned a[4], unsigned b0, unsigned b1) {
    asm volatile(
        "mma.sync.aligned.m16n8k16.row.col.f32.bf16.bf16.f32 "
        "{%0,%1,%2,%3}, {%4,%5,%6,%7}, {%8,%9}, {%0,%1,%2,%3};\n"
        : "+f"(c[0]), "+f"(c[1]), "+f"(c[2]), "+f"(c[3])
        : "r"(a[0]), "r"(a[1]), "r"(a[2]), "r"(a[3]), "r"(b0), "r"(b1));
}
DEVINL unsigned addrA(unsigned base, int lane, int row0, int col0, int pitch) {
    int r = row0 + (lane & 15);
    int c = col0 + ((lane >> 4) << 3);
    return base + (unsigned)(r * pitch + c) * 2u;
}
DEVINL unsigned addrB(unsigned base, int lane, int row0, int col0, int pitch) {
    int r = row0 + ((lane >> 4) << 3) + (lane & 7);
    int c = col0 + (((lane >> 3) & 1) << 3);
    return base + (unsigned)(r * pitch + c) * 2u;
}
DEVINL float ex2f(float x) { float r; asm("ex2.approx.ftz.f32 %0, %1;" : "=f"(r) : "f"(x)); return r; }

DEVINL void cpasync16(unsigned dst, const void* src) {
    asm volatile("cp.async.cg.shared.global [%0], [%1], 16;\n" :: "r"(dst), "l"(src));
}
DEVINL void cp_commit() { asm volatile("cp.async.commit_group;\n" ::); }
DEVINL void cp_wait0()  { asm volatile("cp.async.wait_group 0;\n" ::); }
DEVINL void cp_wait1()  { asm volatile("cp.async.wait_group 1;\n" ::); }

DEVINL void split_bf16(float x, __nv_bfloat16& h, __nv_bfloat16& l) {
    h = __float2bfloat16(x);
    l = __float2bfloat16(x - __bfloat162float(h));
}
DEVINL unsigned pack2(__nv_bfloat16 lo, __nv_bfloat16 hi) {
    return (unsigned)__bfloat16_as_ushort(lo) | ((unsigned)__bfloat16_as_ushort(hi) << 16);
}

// ---------------------------------------------------------------------------
// fp32 -> bf16 hi/lo split (hidden activations)
// ---------------------------------------------------------------------------
__global__ void split_f32(const float* __restrict__ X,
                          __nv_bfloat16* __restrict__ H,
                          __nv_bfloat16* __restrict__ L, int n4)
{
    int i = blockIdx.x * blockDim.x + threadIdx.x;
    if (i >= n4) return;
    float4 v = ((const float4*)X)[i];
    __nv_bfloat16 h0, h1, h2, h3, l0, l1, l2, l3;
    split_bf16(v.x, h0, l0); split_bf16(v.y, h1, l1);
    split_bf16(v.z, h2, l2); split_bf16(v.w, h3, l3);
    *(uint2*)(H + (size_t)i * 4) = make_uint2(pack2(h0, h1), pack2(h2, h3));
    *(uint2*)(L + (size_t)i * 4) = make_uint2(pack2(l0, l1), pack2(l2, l3));
}

// ---------------------------------------------------------------------------
// All four W [K][N] fp32 -> [N][K] bf16 hi/lo in ONE launch (grid.z selects)
// ---------------------------------------------------------------------------
__global__ void transpose_all(
    const float* __restrict__ Wq, const float* __restrict__ Wk,
    const float* __restrict__ Wv, const float* __restrict__ Wo,
    __nv_bfloat16* __restrict__ Wqh, __nv_bfloat16* __restrict__ Wql,
    __nv_bfloat16* __restrict__ Wkh, __nv_bfloat16* __restrict__ Wkl,
    __nv_bfloat16* __restrict__ Wvh, __nv_bfloat16* __restrict__ Wvl,
    __nv_bfloat16* __restrict__ Woh, __nv_bfloat16* __restrict__ Wol)
{
    const int z = blockIdx.z;
    const float* W; __nv_bfloat16 *Th, *Tl; int N;
    if (z == 0)      { W = Wq; Th = Wqh; Tl = Wql; N = HIDDEN; }
    else if (z == 1) { W = Wk; Th = Wkh; Tl = Wkl; N = KVDIM; }
    else if (z == 2) { W = Wv; Th = Wvh; Tl = Wvl; N = KVDIM; }
    else             { W = Wo; Th = Woh; Tl = Wol; N = HIDDEN; }

    int n0 = blockIdx.x * 32, k0 = blockIdx.y * 32;
    if (n0 >= N) return;

    __shared__ float t[32][33];
    int tx = threadIdx.x, ty = threadIdx.y;
#pragma unroll
    for (int i = 0; i < 4; i++)
        t[ty + i * 8][tx] = W[(size_t)(k0 + ty + i * 8) * N + n0 + tx];
    __syncthreads();
#pragma unroll
    for (int i = 0; i < 4; i++) {
        float v = t[tx][ty + i * 8];
        __nv_bfloat16 h, l;
        split_bf16(v, h, l);
        size_t o = (size_t)(n0 + ty + i * 8) * HIDDEN + k0 + tx;
        Th[o] = h; Tl[o] = l;
    }
}

// V [b*S+s][kvh*128+d] fp32 -> Vt [(b*4+kvh)*128+d][s] bf16 hi/lo
__global__ void vt_split(const float* __restrict__ vf,
                         __nv_bfloat16* __restrict__ Th,
                         __nv_bfloat16* __restrict__ Tl)
{
    __shared__ float t[32][33];
    int s0 = blockIdx.x * 32, d0 = blockIdx.y * 32, z = blockIdx.z;
    int b = z >> 2, kvh = z & 3;
    int tx = threadIdx.x, ty = threadIdx.y;
#pragma unroll
    for (int i = 0; i < 4; i++)
        t[ty + i * 8][tx] = vf[(size_t)(b * SEQ + s0 + ty + i * 8) * KVDIM + kvh * 128 + d0 + tx];
    __syncthreads();
#pragma unroll
    for (int i = 0; i < 4; i++) {
        float v = t[tx][ty + i * 8];
        __nv_bfloat16 h, l;
        split_bf16(v, h, l);
        size_t o = (size_t)(z * 128 + d0 + ty + i * 8) * SEQ + s0 + tx;
        Th[o] = h; Tl[o] = l;
    }
}

// ---------------------------------------------------------------------------
// GEMM core (validated): one 128x128 tile of C = (Ah+Al)@(Bh+Bl)^T + bias
// ---------------------------------------------------------------------------
#define KP 40
#define GEMM_TILE_B  (128 * KP * 2)
#define GEMM_STAGE_B (4 * GEMM_TILE_B)
#define GEMM_SMEM    (2 * GEMM_STAGE_B)          // 81920

DEVINL void gemm_tile(
    const __nv_bfloat16* Ah, const __nv_bfloat16* Al,
    const __nv_bfloat16* Bh, const __nv_bfloat16* Bl,
    const float* bias, float* C,
    int m0, int n0loc, int N, int K, char* gsm)
{
    const unsigned sbase = smem_u32(gsm);
    const int tid = threadIdx.x, lane = tid & 31, warp = tid >> 5;
    const int wm = warp >> 2, wn = warp & 3;

    float acc[4][4][4];
#pragma unroll
    for (int i = 0; i < 4; i++)
#pragma unroll
        for (int j = 0; j < 4; j++)
#pragma unroll
            for (int v = 0; v < 4; v++) acc[i][j][v] = 0.f;

    const int nk = K / 32;

    auto issue = [&](int st, int k0) {
        unsigned sb = sbase + (unsigned)st * GEMM_STAGE_B;
#pragma unroll
        for (int l = 0; l < 2; l++) {
            int f = tid + l * 256;
            int row = f >> 2;
            int kc = (f & 3) * 8;
            unsigned so = (unsigned)(row * KP + kc) * 2u;
            size_t goA = (size_t)(m0 + row) * K + k0 + kc;
            size_t goB = (size_t)(n0loc + row) * K + k0 + kc;
            cpasync16(sb + so,                     Ah + goA);
            cpasync16(sb + GEMM_TILE_B + so,       Al + goA);
            cpasync16(sb + 2 * GEMM_TILE_B + so,   Bh + goB);
            cpasync16(sb + 3 * GEMM_TILE_B + so,   Bl + goB);
        }
    };

    issue(0, 0);
    cp_commit();

    for (int kt = 0; kt < nk; kt++) {
        int st = kt & 1;
        if (kt + 1 < nk) { issue(st ^ 1, (kt + 1) * 32); cp_commit(); cp_wait1(); }
        else             { cp_wait0(); }
        __syncthreads();

        unsigned sb  = sbase + (unsigned)st * GEMM_STAGE_B;
        unsigned bAh = sb;
        unsigned bAl = sb + GEMM_TILE_B;
        unsigned bBh = sb + 2 * GEMM_TILE_B;
        unsigned bBl = sb + 3 * GEMM_TILE_B;

#pragma unroll
        for (int ks = 0; ks < 2; ks++) {
            int kb = ks * 16;
            unsigned bh[4][2], bl[4][2];
#pragma unroll
            for (int g = 0; g < 2; g++) {
                unsigned r0, r1, r2, r3;
                ldsm4(r0, r1, r2, r3, addrB(bBh, lane, wn * 32 + g * 16, kb, KP));
                bh[g * 2][0] = r0; bh[g * 2][1] = r1;
                bh[g * 2 + 1][0] = r2; bh[g * 2 + 1][1] = r3;
                ldsm4(r0, r1, r2, r3, addrB(bBl, lane, wn * 32 + g * 16, kb, KP));
                bl[g * 2][0] = r0; bl[g * 2][1] = r1;
                bl[g * 2 + 1][0] = r2; bl[g * 2 + 1][1] = r3;
            }
#pragma unroll
            for (int mf = 0; mf < 4; mf++) {
                unsigned ah[4], al[4];
                ldsm4(ah[0], ah[1], ah[2], ah[3], addrA(bAh, lane, wm * 64 + mf * 16, kb, KP));
                ldsm4(al[0], al[1], al[2], al[3], addrA(bAl, lane, wm * 64 + mf * 16, kb, KP));
#pragma unroll
                for (int nf = 0; nf < 4; nf++) {
                    mma_bf16(acc[mf][nf], ah, bh[nf][0], bh[nf][1]);
                    mma_bf16(acc[mf][nf], ah, bl[nf][0], bl[nf][1]);
                    mma_bf16(acc[mf][nf], al, bh[nf][0], bh[nf][1]);
                }
            }
        }
        __syncthreads();
    }

    const int rb = m0 + wm * 64, cb = n0loc + wn * 32;
#pragma unroll
    for (int mf = 0; mf < 4; mf++)
#pragma unroll
        for (int nf = 0; nf < 4; nf++) {
            int r = rb + mf * 16 + (lane >> 2);
            int c = cb + nf * 8 + (lane & 3) * 2;
            float b0 = bias[c], b1 = bias[c + 1];
            *(float2*)&C[(size_t)r * N + c] =
                make_float2(acc[mf][nf][0] + b0, acc[mf][nf][1] + b1);
            *(float2*)&C[(size_t)(r + 8) * N + c] =
                make_float2(acc[mf][nf][2] + b0, acc[mf][nf][3] + b1);
        }
}

// Merged Q/K/V projection: one launch, grid (24, 32).
__global__ __launch_bounds__(256) void gemm_qkv(
    const __nv_bfloat16* __restrict__ Ah, const __nv_bfloat16* __restrict__ Al,
    const __nv_bfloat16* __restrict__ Wqh, const __nv_bfloat16* __restrict__ Wql,
    const __nv_bfloat16* __restrict__ Wkh, const __nv_bfloat16* __restrict__ Wkl,
    const __nv_bfloat16* __restrict__ Wvh, const __nv_bfloat16* __restrict__ Wvl,
    const float* __restrict__ bq, const float* __restrict__ bk, const float* __restrict__ bv,
    float* __restrict__ qf, float* __restrict__ kf, float* __restrict__ vf)
{
    extern __shared__ char gsm[];
    const int nt = blockIdx.x;
    const int m0 = blockIdx.y * 128;
    const __nv_bfloat16 *Bh, *Bl; const float* bias; float* C; int N, n0;
    if (nt < 16)      { Bh = Wqh; Bl = Wql; bias = bq; C = qf; N = HIDDEN; n0 = nt * 128; }
    else if (nt < 20) { Bh = Wkh; Bl = Wkl; bias = bk; C = kf; N = KVDIM;  n0 = (nt - 16) * 128; }
    else              { Bh = Wvh; Bl = Wvl; bias = bv; C = vf; N = KVDIM;  n0 = (nt - 20) * 128; }
    gemm_tile(Ah, Al, Bh, Bl, bias, C, m0, n0, N, HIDDEN, gsm);
}

__global__ __launch_bounds__(256) void gemm_bf16x3(
    const __nv_bfloat16* __restrict__ Ah, const __nv_bfloat16* __restrict__ Al,
    const __nv_bfloat16* __restrict__ Bh, const __nv_bfloat16* __restrict__ Bl,
    const float* __restrict__ bias, float* __restrict__ C,
    int M, int N, int K)
{
    extern __shared__ char gsm[];
    gemm_tile(Ah, Al, Bh, Bl, bias, C, blockIdx.y * 128, blockIdx.x * 128, N, K, gsm);
}

// ---------------------------------------------------------------------------
// RoPE on Q, K fp32 -> bf16 hi/lo splits (fused); vectorized pair stores
// ---------------------------------------------------------------------------
__global__ __launch_bounds__(128) void rope_split(
    const int* __restrict__ pos_ids,
    const float* __restrict__ qf, const float* __restrict__ kf,
    __nv_bfloat16* __restrict__ Qh, __nv_bfloat16* __restrict__ Ql,
    __nv_bfloat16* __restrict__ Kh, __nv_bfloat16* __restrict__ Kl)
{
    const int bs = blockIdx.x;
    const int t = threadIdx.x;
    __shared__ float cs[64], sn[64];
    if (t < 64) {
        double pos = (double)pos_ids[bs];
        double inv = exp(-((double)t / 64.0) * 13.815510557964274);
        double fr = pos * inv;
        cs[t] = (float)cos(fr);
        sn[t] = (float)sin(fr);
    }
    __syncthreads();

    const float* q = qf + (size_t)bs * HIDDEN;
#pragma unroll
    for (int p = t; p < NHEADS * 32; p += 128) {
        int h = p >> 5, d = (p & 31) * 2;
        size_t base = (size_t)bs * HIDDEN + h * HEADDIM;
        float2 x0 = *(const float2*)(q + h * HEADDIM + d);
        float2 x1 = *(const float2*)(q + h * HEADDIM + d + 64);
        float c0 = cs[d], c1 = cs[d + 1], s0 = sn[d], s1 = sn[d + 1];
        float ya0 = x0.x * c0 - x1.x * s0, ya1 = x0.y * c1 - x1.y * s1;
        float yb0 = x1.x * c0 + x0.x * s0, yb1 = x1.y * c1 + x0.y * s1;
        __nv_bfloat16 ha0, la0, ha1, la1, hb0, lb0, hb1, lb1;
        split_bf16(ya0, ha0, la0); split_bf16(ya1, ha1, la1);
        split_bf16(yb0, hb0, lb0); split_bf16(yb1, hb1, lb1);
        *(unsigned*)&Qh[base + d]      = pack2(ha0, ha1);
        *(unsigned*)&Ql[base + d]      = pack2(la0, la1);
        *(unsigned*)&Qh[base + d + 64] = pack2(hb0, hb1);
        *(unsigned*)&Ql[base + d + 64] = pack2(lb0, lb1);
    }
    const float* k = kf + (size_t)bs * KVDIM;
#pragma unroll
    for (int p = t; p < NKVHEADS * 32; p += 128) {
        int h = p >> 5, d = (p & 31) * 2;
        size_t base = (size_t)bs * KVDIM + h * HEADDIM;
        float2 x0 = *(const float2*)(k + h * HEADDIM + d);
        float2 x1 = *(const float2*)(k + h * HEADDIM + d + 64);
        float c0 = cs[d], c1 = cs[d + 1], s0 = sn[d], s1 = sn[d + 1];
        float ya0 = x0.x * c0 - x1.x * s0, ya1 = x0.y * c1 - x1.y * s1;
        float yb0 = x1.x * c0 + x0.x * s0, yb1 = x1.y * c1 + x0.y * s1;
        __nv_bfloat16 ha0, la0, ha1, la1, hb0, lb0, hb1, lb1;
        split_bf16(ya0, ha0, la0); split_bf16(ya1, ha1, la1);
        split_bf16(yb0, hb0, lb0); split_bf16(yb1, hb1, lb1);
        *(unsigned*)&Kh[base + d]      = pack2(ha0, ha1);
        *(unsigned*)&Kl[base + d]      = pack2(la0, la1);
        *(unsigned*)&Kh[base + d + 64] = pack2(hb0, hb1);
        *(unsigned*)&Kl[base + d + 64] = pack2(lb0, lb1);
    }
}

// ---------------------------------------------------------------------------
// Tensor-core causal flash attention (bf16x3), 2-stage cp.async K/V pipeline.
// Round-14 validated config + LPT dispatch: grid (32 = h|b, 16 = qt slot),
// qt = 15 - blockIdx.y so the longest CTAs are dispatched FIRST.
// ---------------------------------------------------------------------------
#define QP2 136
#define VP2 72
#define AT_OQ  0u
#define AT_OQL 34816u
#define AT_OK  69632u
#define AT_KST 34816u
#define AT_OV  139264u
#define AT_VST 36864u
#define ATTN_SMEM 212992

__global__ __launch_bounds__(256) void attn_mma(
    const __nv_bfloat16* __restrict__ Qh, const __nv_bfloat16* __restrict__ Ql,
    const __nv_bfloat16* __restrict__ Kh, const __nv_bfloat16* __restrict__ Kl,
    const __nv_bfloat16* __restrict__ Vth, const __nv_bfloat16* __restrict__ Vtl,
    __nv_bfloat16* __restrict__ Oh, __nv_bfloat16* __restrict__ Ol)
{
    extern __shared__ __nv_bfloat16 sm[];
    const unsigned sbase = smem_u32(sm);

    const int tid = threadIdx.x, lane = tid & 31, w = tid >> 5;
    // LPT mapping: x = h + 16*b (fastest), y = qt slot with longest first.
    const int h = blockIdx.x & 15, b = blockIdx.x >> 4;
    const int qt = (int)(gridDim.y - 1) - (int)blockIdx.y;
    const int kvh = h >> 2;
    const int vz = b * NKVHEADS + kvh;
    const float L = 0.08838834764831845f * 1.4426950408889634f;

    __nv_bfloat16* sQh = sm;
    __nv_bfloat16* sQl = sm + 128 * QP2;
#pragma unroll
    for (int l = 0; l < 8; l++) {
        int f = tid + l * 256;
        int row = f >> 4, dc = (f & 15) * 8;
        size_t go = (size_t)(b * SEQ + qt * 128 + row) * HIDDEN + h * 128 + dc;
        *(uint4*)&sQh[row * QP2 + dc] = *(const uint4*)(Qh + go);
        *(uint4*)&sQl[row * QP2 + dc] = *(const uint4*)(Ql + go);
    }

    auto issue_kv = [&](int st, int kv0) {
        unsigned kb = sbase + AT_OK + (unsigned)st * AT_KST;
        unsigned vb = sbase + AT_OV + (unsigned)st * AT_VST;
#pragma unroll
        for (int l = 0; l < 4; l++) {
            int f = tid + l * 256;
            int row = f >> 4, dc = (f & 15) * 8;
            unsigned so = (unsigned)(row * QP2 + dc) * 2u;
            size_t go = (size_t)(b * SEQ + kv0 + row) * KVDIM + kvh * 128 + dc;
            cpasync16(kb + so,          Kh + go);
            cpasync16(kb + 17408u + so, Kl + go);
        }
#pragma unroll
        for (int l = 0; l < 4; l++) {
            int f = tid + l * 256;
            int row = f >> 3, c = (f & 7) * 8;
            unsigned so = (unsigned)(row * VP2 + c) * 2u;
            size_t go = (size_t)(vz * 128 + row) * SEQ + kv0 + c;
            cpasync16(vb + so,          Vth + go);
            cpasync16(vb + 18432u + so, Vtl + go);
        }
    };

    float O[16][4];
#pragma unroll
    for (int i = 0; i < 16; i++)
#pragma unroll
        for (int v = 0; v < 4; v++) O[i][v] = 0.f;
    float m0 = -1e30f, m1 = -1e30f, l0 = 0.f, l1 = 0.f;

    const int nkv = (qt + 1) * 128;
    const int wrow = qt * 128 + w * 16;

    issue_kv(0, 0);
    cp_commit();

    for (int kv0 = 0, it = 0; kv0 < nkv; kv0 += 64, it ^= 1) {
        if (kv0 + 64 < nkv) { issue_kv(it ^ 1, kv0 + 64); cp_commit(); cp_wait1(); }
        else                { cp_wait0(); }
        __syncthreads();

        const unsigned bKh = sbase + AT_OK + (unsigned)it * AT_KST;
        const unsigned bKl = bKh + 17408u;
        const unsigned bVh = sbase + AT_OV + (unsigned)it * AT_VST;
        const unsigned bVl = bVh + 18432u;
        const unsigned bQh = sbase + AT_OQ;
        const unsigned bQl = sbase + AT_OQL;

        float S[8][4];
#pragma unroll
        for (int i = 0; i < 8; i++)
#pragma unroll
            for (int v = 0; v < 4; v++) S[i][v] = 0.f;
#pragma unroll
        for (int kc = 0; kc < 8; kc++) {
            unsigned qh[4], ql[4];
            ldsm4(qh[0], qh[1], qh[2], qh[3], addrA(bQh, lane, w * 16, kc * 16, QP2));
            ldsm4(ql[0], ql[1], ql[2], ql[3], addrA(bQl, lane, w * 16, kc * 16, QP2));
#pragma unroll
            for (int nn = 0; nn < 4; nn++) {
                unsigned kh[4], kl[4];
                ldsm4(kh[0], kh[1], kh[2], kh[3], addrB(bKh, lane, nn * 16, kc * 16, QP2));
                ldsm4(kl[0], kl[1], kl[2], kl[3], addrB(bKl, lane, nn * 16, kc * 16, QP2));
                mma_bf16(S[nn * 2], qh, kh[0], kh[1]);
                mma_bf16(S[nn * 2], qh, kl[0], kl[1]);
                mma_bf16(S[nn * 2], ql, kh[0], kh[1]);
                mma_bf16(S[nn * 2 + 1], qh, kh[2], kh[3]);
                mma_bf16(S[nn * 2 + 1], qh, kl[2], kl[3]);
                mma_bf16(S[nn * 2 + 1], ql, kh[2], kh[3]);
            }
        }

        const int r0g = wrow + (lane >> 2);
        const int r1g = r0g + 8;
        if (kv0 + 63 > wrow) {
#pragma unroll
            for (int nf = 0; nf < 8; nf++) {
                int c = kv0 + nf * 8 + (lane & 3) * 2;
                if (c > r0g) S[nf][0] = -1e30f;
                if (c + 1 > r0g) S[nf][1] = -1e30f;
                if (c > r1g) S[nf][2] = -1e30f;
                if (c + 1 > r1g) S[nf][3] = -1e30f;
            }
        }

        float t0 = -1e30f, t1 = -1e30f;
#pragma unroll
        for (int nf = 0; nf < 8; nf++) {
            t0 = fmaxf(t0, fmaxf(S[nf][0], S[nf][1]));
            t1 = fmaxf(t1, fmaxf(S[nf][2], S[nf][3]));
        }
        t0 = fmaxf(t0, __shfl_xor_sync(0xffffffffu, t0, 1));
        t0 = fmaxf(t0, __shfl_xor_sync(0xffffffffu, t0, 2));
        t1 = fmaxf(t1, __shfl_xor_sync(0xffffffffu, t1, 1));
        t1 = fmaxf(t1, __shfl_xor_sync(0xffffffffu, t1, 2));
        float mn0 = fmaxf(m0, t0), mn1 = fmaxf(m1, t1);
        float c0 = ex2f((m0 - mn0) * L), c1 = ex2f((m1 - mn1) * L);
        m0 = mn0; m1 = mn1;
        float rs0 = 0.f, rs1 = 0.f;
#pragma unroll
        for (int nf = 0; nf < 8; nf++) {
            S[nf][0] = ex2f((S[nf][0] - mn0) * L);
            S[nf][1] = ex2f((S[nf][1] - mn0) * L);
            S[nf][2] = ex2f((S[nf][2] - mn1) * L);
            S[nf][3] = ex2f((S[nf][3] - mn1) * L);
            rs0 += S[nf][0] + S[nf][1];
            rs1 += S[nf][2] + S[nf][3];
        }
        rs0 += __shfl_xor_sync(0xffffffffu, rs0, 1);
        rs0 += __shfl_xor_sync(0xffffffffu, rs0, 2);
        rs1 += __shfl_xor_sync(0xffffffffu, rs1, 1);
        rs1 += __shfl_xor_sync(0xffffffffu, rs1, 2);
        l0 = l0 * c0 + rs0;
        l1 = l1 * c1 + rs1;
#pragma unroll
        for (int i = 0; i < 16; i++) {
            O[i][0] *= c0; O[i][1] *= c0; O[i][2] *= c1; O[i][3] *= c1;
        }

#pragma unroll
        for (int kc = 0; kc < 4; kc++) {
            unsigned ah[4], al[4];
#pragma unroll
            for (int g = 0; g < 2; g++) {
                const float* s4 = S[kc * 2 + g];
                __nv_bfloat16 h0, l0b, h1, l1b, h2, l2b, h3, l3b;
                split_bf16(s4[0], h0, l0b); split_bf16(s4[1], h1, l1b);
                split_bf16(s4[2], h2, l2b); split_bf16(s4[3], h3, l3b);
                ah[g * 2]     = pack2(h0, h1); al[g * 2]     = pack2(l0b, l1b);
                ah[g * 2 + 1] = pack2(h2, h3); al[g * 2 + 1] = pack2(l2b, l3b);
            }
#pragma unroll
            for (int dn = 0; dn < 8; dn++) {
                unsigned vh[4], vl[4];
                ldsm4(vh[0], vh[1], vh[2], vh[3], addrB(bVh, lane, dn * 16, kc * 16, VP2));
                ldsm4(vl[0], vl[1], vl[2], vl[3], addrB(bVl, lane, dn * 16, kc * 16, VP2));
                mma_bf16(O[dn * 2], ah, vh[0], vh[1]);
                mma_bf16(O[dn * 2], ah, vl[0], vl[1]);
                mma_bf16(O[dn * 2], al, vh[0], vh[1]);
                mma_bf16(O[dn * 2 + 1], ah, vh[2], vh[3]);
                mma_bf16(O[dn * 2 + 1], ah, vl[2], vl[3]);
                mma_bf16(O[dn * 2 + 1], al, vh[2], vh[3]);
            }
        }
        __syncthreads();
    }

    float i0 = 1.f / l0, i1 = 1.f / l1;
    const int row0 = b * SEQ + wrow + (lane >> 2);
#pragma unroll
    for (int nf = 0; nf < 16; nf++) {
        int c = h * 128 + nf * 8 + (lane & 3) * 2;
        float a0 = O[nf][0] * i0, a1 = O[nf][1] * i0;
        float a2 = O[nf][2] * i1, a3 = O[nf][3] * i1;
        __nv_bfloat16 h0, l0b, h1, l1b, h2, l2b, h3, l3b;
        split_bf16(a0, h0, l0b); split_bf16(a1, h1, l1b);
        split_bf16(a2, h2, l2b); split_bf16(a3, h3, l3b);
        *(unsigned*)&Oh[(size_t)row0 * HIDDEN + c] = pack2(h0, h1);
        *(unsigned*)&Ol[(size_t)row0 * HIDDEN + c] = pack2(l0b, l1b);
        *(unsigned*)&Oh[(size_t)(row0 + 8) * HIDDEN + c] = pack2(h2, h3);
        *(unsigned*)&Ol[(size_t)(row0 + 8) * HIDDEN + c] = pack2(l2b, l3b);
    }
}

// ---------------------------------------------------------------------------
// Launch
// ---------------------------------------------------------------------------
extern "C" void kernel_launch(void* const* d_in, const int* in_sizes, int n_in,
                              void* d_out, int out_size)
{
    const float* hidden = (const float*)d_in[0];
    const int*   posids = (const int*)d_in[1];
    const float* Wq = (const float*)d_in[2];
    const float* bq = (const float*)d_in[3];
    const float* Wk = (const float*)d_in[4];
    const float* bk = (const float*)d_in[5];
    const float* Wv = (const float*)d_in[6];
    const float* bv = (const float*)d_in[7];
    const float* Wo = (const float*)d_in[8];
    const float* bo = (const float*)d_in[9];
    float* out = (float*)d_out;

    __nv_bfloat16 *Hh, *Hl, *Wqh, *Wql, *Wkh, *Wkl, *Wvh, *Wvl, *Woh, *Wol, *Ah, *Al;
    __nv_bfloat16 *Qh, *Ql, *Kh, *Kl, *Vth, *Vtl;
    float *qf, *kf, *vf;
    cudaGetSymbolAddress((void**)&Hh, g_Hh);   cudaGetSymbolAddress((void**)&Hl, g_Hl);
    cudaGetSymbolAddress((void**)&Wqh, g_Wqt_h); cudaGetSymbolAddress((void**)&Wql, g_Wqt_l);
    cudaGetSymbolAddress((void**)&Wkh, g_Wkt_h); cudaGetSymbolAddress((void**)&Wkl, g_Wkt_l);
    cudaGetSymbolAddress((void**)&Wvh, g_Wvt_h); cudaGetSymbolAddress((void**)&Wvl, g_Wvt_l);
    cudaGetSymbolAddress((void**)&Woh, g_Wot_h); cudaGetSymbolAddress((void**)&Wol, g_Wot_l);
    cudaGetSymbolAddress((void**)&Ah, g_Ah);   cudaGetSymbolAddress((void**)&Al, g_Al);
    cudaGetSymbolAddress((void**)&Qh, g_Qh);   cudaGetSymbolAddress((void**)&Ql, g_Ql);
    cudaGetSymbolAddress((void**)&Kh, g_Kh);   cudaGetSymbolAddress((void**)&Kl, g_Kl);
    cudaGetSymbolAddress((void**)&Vth, g_Vth); cudaGetSymbolAddress((void**)&Vtl, g_Vtl);
    cudaGetSymbolAddress((void**)&qf, g_qf);   cudaGetSymbolAddress((void**)&kf, g_kf);
    cudaGetSymbolAddress((void**)&vf, g_vf);

    // idx 0: split hidden
    split_f32<<<(MROWS * HIDDEN / 4 + 255) / 256, 256>>>(hidden, Hh, Hl, MROWS * HIDDEN / 4);
    // idx 1: all weight transposes in one launch
    transpose_all<<<dim3(HIDDEN / 32, HIDDEN / 32, 4), dim3(32, 8)>>>(
        Wq, Wk, Wv, Wo, Wqh, Wql, Wkh, Wkl, Wvh, Wvl, Woh, Wol);

    // idx 2: merged Q/K/V projection (wave-packed)
    cudaFuncSetAttribute(gemm_qkv, cudaFuncAttributeMaxDynamicSharedMemorySize, GEMM_SMEM);
    cudaFuncSetAttribute(gemm_bf16x3, cudaFuncAttributeMaxDynamicSharedMemorySize, GEMM_SMEM);
    gemm_qkv<<<dim3(24, MROWS / 128), 256, GEMM_SMEM>>>(
        Hh, Hl, Wqh, Wql, Wkh, Wkl, Wvh, Wvl, bq, bk, bv, qf, kf, vf);

    // idx 3: fused RoPE + split ; idx 4: V transpose + split
    rope_split<<<MROWS, 128>>>(posids, qf, kf, Qh, Ql, Kh, Kl);
    vt_split<<<dim3(SEQ / 32, HEADDIM / 32, BATCH * NKVHEADS), dim3(32, 8)>>>(vf, Vth, Vtl);

    // idx 5: attention — LPT grid: x = (h,b), y = qt slot (longest first)
    cudaFuncSetAttribute(attn_mma, cudaFuncAttributeMaxDynamicSharedMemorySize, ATTN_SMEM);
    attn_mma<<<dim3(NHEADS * BATCH, SEQ / 128), 256, ATTN_SMEM>>>(Qh, Ql, Kh, Kl, Vth, Vtl, Ah, Al);

    // idx 6: output projection
    gemm_bf16x3<<<dim3(HIDDEN / 128, MROWS / 128), 256, GEMM_SMEM>>>(Ah, Al, Woh, Wol, bo, out, MROWS, HIDDEN, HIDDEN);
}

// round 16
// speedup vs baseline: 1.1411x; 1.0173x over previous
#include <cuda_runtime.h>
#include <cuda_bf16.h>
#include <math.h>
#include <stdint.h>

#define HIDDEN   2048
#define NHEADS   16
#define NKVHEADS 4
#define HEADDIM  128
#define BATCH    2
#define SEQ      2048
#define MROWS    (BATCH * SEQ)          // 4096
#define KVDIM    (NKVHEADS * HEADDIM)   // 512

#define DEVINL __device__ __forceinline__

// ---------------------------------------------------------------------------
// Scratch
// ---------------------------------------------------------------------------
__device__ __nv_bfloat16 g_Hh[MROWS * HIDDEN], g_Hl[MROWS * HIDDEN];
__device__ __nv_bfloat16 g_Wqt_h[HIDDEN * HIDDEN], g_Wqt_l[HIDDEN * HIDDEN];
__device__ __nv_bfloat16 g_Wkt_h[KVDIM * HIDDEN],  g_Wkt_l[KVDIM * HIDDEN];
__device__ __nv_bfloat16 g_Wvt_h[KVDIM * HIDDEN],  g_Wvt_l[KVDIM * HIDDEN];
__device__ __nv_bfloat16 g_Wot_h[HIDDEN * HIDDEN], g_Wot_l[HIDDEN * HIDDEN];
__device__ float g_qf[MROWS * HIDDEN];
__device__ float g_kf[MROWS * KVDIM];
__device__ float g_vf[MROWS * KVDIM];
__device__ __nv_bfloat16 g_Ah[MROWS * HIDDEN], g_Al[MROWS * HIDDEN];
__device__ __nv_bfloat16 g_Qh[MROWS * HIDDEN], g_Ql[MROWS * HIDDEN];
__device__ __nv_bfloat16 g_Kh[MROWS * KVDIM],  g_Kl[MROWS * KVDIM];
__device__ __nv_bfloat16 g_Vth[BATCH * KVDIM * SEQ], g_Vtl[BATCH * KVDIM * SEQ]; // [z*128+d][s]

// ---------------------------------------------------------------------------
// PTX helpers
// ---------------------------------------------------------------------------
DEVINL unsigned smem_u32(const void* p) { return (unsigned)__cvta_generic_to_shared(p); }

DEVINL void ldsm4(unsigned& r0, unsigned& r1, unsigned& r2, unsigned& r3, unsigned a) {
    asm volatile("ldmatrix.sync.aligned.m8n8.x4.shared.b16 {%0,%1,%2,%3}, [%4];\n"
                 : "=r"(r0), "=r"(r1), "=r"(r2), "=r"(r3) : "r"(a));
}
DEVINL void mma_bf16(float c[4], const unsigned a[4], unsigned b0, unsigned b1) {
    asm volatile(
        "mma.sync.aligned.m16n8k16.row.col.f32.bf16.bf16.f32 "
        "{%0,%1,%2,%3}, {%4,%5,%6,%7}, {%8,%9}, {%0,%1,%2,%3};\n"
        : "+f"(c[0]), "+f"(c[1]), "+f"(c[2]), "+f"(c[3])
        : "r"(a[0]), "r"(a[1]), "r"(a[2]), "r"(a[3]), "r"(b0), "r"(b1));
}
DEVINL unsigned addrA(unsigned base, int lane, int row0, int col0, int pitch) {
    int r = row0 + (lane & 15);
    int c = col0 + ((lane >> 4) << 3);
    return base + (unsigned)(r * pitch + c) * 2u;
}
DEVINL unsigned addrB(unsigned base, int lane, int row0, int col0, int pitch) {
    int r = row0 + ((lane >> 4) << 3) + (lane & 7);
    int c = col0 + (((lane >> 3) & 1) << 3);
    return base + (unsigned)(r * pitch + c) * 2u;
}
DEVINL float ex2f(float x) { float r; asm("ex2.approx.ftz.f32 %0, %1;" : "=f"(r) : "f"(x)); return r; }

DEVINL void cpasync16(unsigned dst, const void* src) {
    asm volatile("cp.async.cg.shared.global [%0], [%1], 16;\n" :: "r"(dst), "l"(src));
}
DEVINL void cp_commit() { asm volatile("cp.async.commit_group;\n" ::); }
DEVINL void cp_wait0()  { asm volatile("cp.async.wait_group 0;\n" ::); }
DEVINL void cp_wait1()  { asm volatile("cp.async.wait_group 1;\n" ::); }

DEVINL void split_bf16(float x, __nv_bfloat16& h, __nv_bfloat16& l) {
    h = __float2bfloat16(x);
    l = __float2bfloat16(x - __bfloat162float(h));
}
DEVINL unsigned pack2(__nv_bfloat16 lo, __nv_bfloat16 hi) {
    return (unsigned)__bfloat16_as_ushort(lo) | ((unsigned)__bfloat16_as_ushort(hi) << 16);
}

// ---------------------------------------------------------------------------
// fp32 -> bf16 hi/lo split (hidden activations)
// ---------------------------------------------------------------------------
__global__ void split_f32(const float* __restrict__ X,
                          __nv_bfloat16* __restrict__ H,
                          __nv_bfloat16* __restrict__ L, int n4)
{
    int i = blockIdx.x * blockDim.x + threadIdx.x;
    if (i >= n4) return;
    float4 v = ((const float4*)X)[i];
    __nv_bfloat16 h0, h1, h2, h3, l0, l1, l2, l3;
    split_bf16(v.x, h0, l0); split_bf16(v.y, h1, l1);
    split_bf16(v.z, h2, l2); split_bf16(v.w, h3, l3);
    *(uint2*)(H + (size_t)i * 4) = make_uint2(pack2(h0, h1), pack2(h2, h3));
    *(uint2*)(L + (size_t)i * 4) = make_uint2(pack2(l0, l1), pack2(l2, l3));
}

// ---------------------------------------------------------------------------
// All four W [K][N] fp32 -> [N][K] bf16 hi/lo in ONE launch (grid.z selects)
// ---------------------------------------------------------------------------
__global__ void transpose_all(
    const float* __restrict__ Wq, const float* __restrict__ Wk,
    const float* __restrict__ Wv, const float* __restrict__ Wo,
    __nv_bfloat16* __restrict__ Wqh, __nv_bfloat16* __restrict__ Wql,
    __nv_bfloat16* __restrict__ Wkh, __nv_bfloat16* __restrict__ Wkl,
    __nv_bfloat16* __restrict__ Wvh, __nv_bfloat16* __restrict__ Wvl,
    __nv_bfloat16* __restrict__ Woh, __nv_bfloat16* __restrict__ Wol)
{
    const int z = blockIdx.z;
    const float* W; __nv_bfloat16 *Th, *Tl; int N;
    if (z == 0)      { W = Wq; Th = Wqh; Tl = Wql; N = HIDDEN; }
    else if (z == 1) { W = Wk; Th = Wkh; Tl = Wkl; N = KVDIM; }
    else if (z == 2) { W = Wv; Th = Wvh; Tl = Wvl; N = KVDIM; }
    else             { W = Wo; Th = Woh; Tl = Wol; N = HIDDEN; }

    int n0 = blockIdx.x * 32, k0 = blockIdx.y * 32;
    if (n0 >= N) return;

    __shared__ float t[32][33];
    int tx = threadIdx.x, ty = threadIdx.y;
#pragma unroll
    for (int i = 0; i < 4; i++)
        t[ty + i * 8][tx] = W[(size_t)(k0 + ty + i * 8) * N + n0 + tx];
    __syncthreads();
#pragma unroll
    for (int i = 0; i < 4; i++) {
        float v = t[tx][ty + i * 8];
        __nv_bfloat16 h, l;
        split_bf16(v, h, l);
        size_t o = (size_t)(n0 + ty + i * 8) * HIDDEN + k0 + tx;
        Th[o] = h; Tl[o] = l;
    }
}

// ---------------------------------------------------------------------------
// Merged RoPE-split (blocks 0..2047, 2 rows each) + V-transpose-split
// (blocks 2048..4095). 256 threads.
// RoPE phase: fp64 exp + fp64 multiply, then hi/lo split + sincosf(hi) with
// first-order correction (error ~1e-7 rad; replaces fp64 sin/cos chains).
// ---------------------------------------------------------------------------
__global__ __launch_bounds__(256) void prep_rope_vt(
    const int* __restrict__ pos_ids,
    const float* __restrict__ qf, const float* __restrict__ kf,
    const float* __restrict__ vf,
    __nv_bfloat16* __restrict__ Qh, __nv_bfloat16* __restrict__ Ql,
    __nv_bfloat16* __restrict__ Kh, __nv_bfloat16* __restrict__ Kl,
    __nv_bfloat16* __restrict__ Vth, __nv_bfloat16* __restrict__ Vtl)
{
    __shared__ float cs[2][64], sn[2][64];
    __shared__ float tt[32][33];

    const int bx = blockIdx.x;
    const int tid = threadIdx.x;

    if (bx < MROWS / 2) {
        // ---- RoPE + split: half-block per bs row ----
        const int half = tid >> 7;          // 0 or 1
        const int ht = tid & 127;
        const int bs = bx * 2 + half;
        if (ht < 64) {
            double pos = (double)pos_ids[bs];
            double inv = exp(-((double)ht / 64.0) * 13.815510557964274);
            double phi = pos * inv;
            float phi_hi = (float)phi;
            float phi_lo = (float)(phi - (double)phi_hi);
            float sh, ch;
            sincosf(phi_hi, &sh, &ch);
            sn[half][ht] = sh + ch * phi_lo;
            cs[half][ht] = ch - sh * phi_lo;
        }
        __syncthreads();

        const float* q = qf + (size_t)bs * HIDDEN;
#pragma unroll
        for (int p = ht; p < NHEADS * 32; p += 128) {
            int h = p >> 5, d = (p & 31) * 2;
            size_t base = (size_t)bs * HIDDEN + h * HEADDIM;
            float2 x0 = *(const float2*)(q + h * HEADDIM + d);
            float2 x1 = *(const float2*)(q + h * HEADDIM + d + 64);
            float c0 = cs[half][d], c1 = cs[half][d + 1];
            float s0 = sn[half][d], s1 = sn[half][d + 1];
            float ya0 = x0.x * c0 - x1.x * s0, ya1 = x0.y * c1 - x1.y * s1;
            float yb0 = x1.x * c0 + x0.x * s0, yb1 = x1.y * c1 + x0.y * s1;
            __nv_bfloat16 ha0, la0, ha1, la1, hb0, lb0, hb1, lb1;
            split_bf16(ya0, ha0, la0); split_bf16(ya1, ha1, la1);
            split_bf16(yb0, hb0, lb0); split_bf16(yb1, hb1, lb1);
            *(unsigned*)&Qh[base + d]      = pack2(ha0, ha1);
            *(unsigned*)&Ql[base + d]      = pack2(la0, la1);
            *(unsigned*)&Qh[base + d + 64] = pack2(hb0, hb1);
            *(unsigned*)&Ql[base + d + 64] = pack2(lb0, lb1);
        }
        const float* k = kf + (size_t)bs * KVDIM;
#pragma unroll
        for (int p = ht; p < NKVHEADS * 32; p += 128) {
            int h = p >> 5, d = (p & 31) * 2;
            size_t base = (size_t)bs * KVDIM + h * HEADDIM;
            float2 x0 = *(const float2*)(k + h * HEADDIM + d);
            float2 x1 = *(const float2*)(k + h * HEADDIM + d + 64);
            float c0 = cs[half][d], c1 = cs[half][d + 1];
            float s0 = sn[half][d], s1 = sn[half][d + 1];
            float ya0 = x0.x * c0 - x1.x * s0, ya1 = x0.y * c1 - x1.y * s1;
            float yb0 = x1.x * c0 + x0.x * s0, yb1 = x1.y * c1 + x0.y * s1;
            __nv_bfloat16 ha0, la0, ha1, la1, hb0, lb0, hb1, lb1;
            split_bf16(ya0, ha0, la0); split_bf16(ya1, ha1, la1);
            split_bf16(yb0, hb0, lb0); split_bf16(yb1, hb1, lb1);
            *(unsigned*)&Kh[base + d]      = pack2(ha0, ha1);
            *(unsigned*)&Kl[base + d]      = pack2(la0, la1);
            *(unsigned*)&Kh[base + d + 64] = pack2(hb0, hb1);
            *(unsigned*)&Kl[base + d + 64] = pack2(lb0, lb1);
        }
    } else {
        // ---- V transpose + split (one 32x32 tile) ----
        int vi = bx - MROWS / 2;
        int s0 = (vi & 63) * 32;
        int d0 = ((vi >> 6) & 3) * 32;
        int z = vi >> 8;                   // 0..7 = b*4+kvh
        int b = z >> 2, kvh = z & 3;
        int tx = tid & 31, ty = tid >> 5;  // (32, 8)
#pragma unroll
        for (int i = 0; i < 4; i++)
            tt[ty + i * 8][tx] =
                vf[(size_t)(b * SEQ + s0 + ty + i * 8) * KVDIM + kvh * 128 + d0 + tx];
        __syncthreads();
#pragma unroll
        for (int i = 0; i < 4; i++) {
            float v = tt[tx][ty + i * 8];
            __nv_bfloat16 h, l;
            split_bf16(v, h, l);
            size_t o = (size_t)(z * 128 + d0 + ty + i * 8) * SEQ + s0 + tx;
            Vth[o] = h; Vtl[o] = l;
        }
    }
}

// ---------------------------------------------------------------------------
// GEMM core (validated): one 128x128 tile of C = (Ah+Al)@(Bh+Bl)^T + bias
// ---------------------------------------------------------------------------
#define KP 40
#define GEMM_TILE_B  (128 * KP * 2)
#define GEMM_STAGE_B (4 * GEMM_TILE_B)
#define GEMM_SMEM    (2 * GEMM_STAGE_B)          // 81920

DEVINL void gemm_tile(
    const __nv_bfloat16* Ah, const __nv_bfloat16* Al,
    const __nv_bfloat16* Bh, const __nv_bfloat16* Bl,
    const float* bias, float* C,
    int m0, int n0loc, int N, int K, char* gsm)
{
    const unsigned sbase = smem_u32(gsm);
    const int tid = threadIdx.x, lane = tid & 31, warp = tid >> 5;
    const int wm = warp >> 2, wn = warp & 3;

    float acc[4][4][4];
#pragma unroll
    for (int i = 0; i < 4; i++)
#pragma unroll
        for (int j = 0; j < 4; j++)
#pragma unroll
            for (int v = 0; v < 4; v++) acc[i][j][v] = 0.f;

    const int nk = K / 32;

    auto issue = [&](int st, int k0) {
        unsigned sb = sbase + (unsigned)st * GEMM_STAGE_B;
#pragma unroll
        for (int l = 0; l < 2; l++) {
            int f = tid + l * 256;
            int row = f >> 2;
            int kc = (f & 3) * 8;
            unsigned so = (unsigned)(row * KP + kc) * 2u;
            size_t goA = (size_t)(m0 + row) * K + k0 + kc;
            size_t goB = (size_t)(n0loc + row) * K + k0 + kc;
            cpasync16(sb + so,                     Ah + goA);
            cpasync16(sb + GEMM_TILE_B + so,       Al + goA);
            cpasync16(sb + 2 * GEMM_TILE_B + so,   Bh + goB);
            cpasync16(sb + 3 * GEMM_TILE_B + so,   Bl + goB);
        }
    };

    issue(0, 0);
    cp_commit();

    for (int kt = 0; kt < nk; kt++) {
        int st = kt & 1;
        if (kt + 1 < nk) { issue(st ^ 1, (kt + 1) * 32); cp_commit(); cp_wait1(); }
        else             { cp_wait0(); }
        __syncthreads();

        unsigned sb  = sbase + (unsigned)st * GEMM_STAGE_B;
        unsigned bAh = sb;
        unsigned bAl = sb + GEMM_TILE_B;
        unsigned bBh = sb + 2 * GEMM_TILE_B;
        unsigned bBl = sb + 3 * GEMM_TILE_B;

#pragma unroll
        for (int ks = 0; ks < 2; ks++) {
            int kb = ks * 16;
            unsigned bh[4][2], bl[4][2];
#pragma unroll
            for (int g = 0; g < 2; g++) {
                unsigned r0, r1, r2, r3;
                ldsm4(r0, r1, r2, r3, addrB(bBh, lane, wn * 32 + g * 16, kb, KP));
                bh[g * 2][0] = r0; bh[g * 2][1] = r1;
                bh[g * 2 + 1][0] = r2; bh[g * 2 + 1][1] = r3;
                ldsm4(r0, r1, r2, r3, addrB(bBl, lane, wn * 32 + g * 16, kb, KP));
                bl[g * 2][0] = r0; bl[g * 2][1] = r1;
                bl[g * 2 + 1][0] = r2; bl[g * 2 + 1][1] = r3;
            }
#pragma unroll
            for (int mf = 0; mf < 4; mf++) {
                unsigned ah[4], al[4];
                ldsm4(ah[0], ah[1], ah[2], ah[3], addrA(bAh, lane, wm * 64 + mf * 16, kb, KP));
                ldsm4(al[0], al[1], al[2], al[3], addrA(bAl, lane, wm * 64 + mf * 16, kb, KP));
#pragma unroll
                for (int nf = 0; nf < 4; nf++) {
                    mma_bf16(acc[mf][nf], ah, bh[nf][0], bh[nf][1]);
                    mma_bf16(acc[mf][nf], ah, bl[nf][0], bl[nf][1]);
                    mma_bf16(acc[mf][nf], al, bh[nf][0], bh[nf][1]);
                }
            }
        }
        __syncthreads();
    }

    const int rb = m0 + wm * 64, cb = n0loc + wn * 32;
#pragma unroll
    for (int mf = 0; mf < 4; mf++)
#pragma unroll
        for (int nf = 0; nf < 4; nf++) {
            int r = rb + mf * 16 + (lane >> 2);
            int c = cb + nf * 8 + (lane & 3) * 2;
            float b0 = bias[c], b1 = bias[c + 1];
            *(float2*)&C[(size_t)r * N + c] =
                make_float2(acc[mf][nf][0] + b0, acc[mf][nf][1] + b1);
            *(float2*)&C[(size_t)(r + 8) * N + c] =
                make_float2(acc[mf][nf][2] + b0, acc[mf][nf][3] + b1);
        }
}

// Merged Q/K/V projection: one launch, grid (24, 32).
__global__ __launch_bounds__(256) void gemm_qkv(
    const __nv_bfloat16* __restrict__ Ah, const __nv_bfloat16* __restrict__ Al,
    const __nv_bfloat16* __restrict__ Wqh, const __nv_bfloat16* __restrict__ Wql,
    const __nv_bfloat16* __restrict__ Wkh, const __nv_bfloat16* __restrict__ Wkl,
    const __nv_bfloat16* __restrict__ Wvh, const __nv_bfloat16* __restrict__ Wvl,
    const float* __restrict__ bq, const float* __restrict__ bk, const float* __restrict__ bv,
    float* __restrict__ qf, float* __restrict__ kf, float* __restrict__ vf)
{
    extern __shared__ char gsm[];
    const int nt = blockIdx.x;
    const int m0 = blockIdx.y * 128;
    const __nv_bfloat16 *Bh, *Bl; const float* bias; float* C; int N, n0;
    if (nt < 16)      { Bh = Wqh; Bl = Wql; bias = bq; C = qf; N = HIDDEN; n0 = nt * 128; }
    else if (nt < 20) { Bh = Wkh; Bl = Wkl; bias = bk; C = kf; N = KVDIM;  n0 = (nt - 16) * 128; }
    else              { Bh = Wvh; Bl = Wvl; bias = bv; C = vf; N = KVDIM;  n0 = (nt - 20) * 128; }
    gemm_tile(Ah, Al, Bh, Bl, bias, C, m0, n0, N, HIDDEN, gsm);
}

__global__ __launch_bounds__(256) void gemm_bf16x3(
    const __nv_bfloat16* __restrict__ Ah, const __nv_bfloat16* __restrict__ Al,
    const __nv_bfloat16* __restrict__ Bh, const __nv_bfloat16* __restrict__ Bl,
    const float* __restrict__ bias, float* __restrict__ C,
    int M, int N, int K)
{
    extern __shared__ char gsm[];
    gemm_tile(Ah, Al, Bh, Bl, bias, C, blockIdx.y * 128, blockIdx.x * 128, N, K, gsm);
}

// ---------------------------------------------------------------------------
// Tensor-core causal flash attention (bf16x3), 2-stage cp.async K/V pipeline.
// LPT dispatch: grid (32 = h|b, 16 = qt slot), qt = 15 - blockIdx.y.
// ---------------------------------------------------------------------------
#define QP2 136
#define VP2 72
#define AT_OQ  0u
#define AT_OQL 34816u
#define AT_OK  69632u
#define AT_KST 34816u
#define AT_OV  139264u
#define AT_VST 36864u
#define ATTN_SMEM 212992

__global__ __launch_bounds__(256) void attn_mma(
    const __nv_bfloat16* __restrict__ Qh, const __nv_bfloat16* __restrict__ Ql,
    const __nv_bfloat16* __restrict__ Kh, const __nv_bfloat16* __restrict__ Kl,
    const __nv_bfloat16* __restrict__ Vth, const __nv_bfloat16* __restrict__ Vtl,
    __nv_bfloat16* __restrict__ Oh, __nv_bfloat16* __restrict__ Ol)
{
    extern __shared__ __nv_bfloat16 sm[];
    const unsigned sbase = smem_u32(sm);

    const int tid = threadIdx.x, lane = tid & 31, w = tid >> 5;
    const int h = blockIdx.x & 15, b = blockIdx.x >> 4;
    const int qt = (int)(gridDim.y - 1) - (int)blockIdx.y;
    const int kvh = h >> 2;
    const int vz = b * NKVHEADS + kvh;
    const float L = 0.08838834764831845f * 1.4426950408889634f;

    __nv_bfloat16* sQh = sm;
    __nv_bfloat16* sQl = sm + 128 * QP2;
#pragma unroll
    for (int l = 0; l < 8; l++) {
        int f = tid + l * 256;
        int row = f >> 4, dc = (f & 15) * 8;
        size_t go = (size_t)(b * SEQ + qt * 128 + row) * HIDDEN + h * 128 + dc;
        *(uint4*)&sQh[row * QP2 + dc] = *(const uint4*)(Qh + go);
        *(uint4*)&sQl[row * QP2 + dc] = *(const uint4*)(Ql + go);
    }

    auto issue_kv = [&](int st, int kv0) {
        unsigned kb = sbase + AT_OK + (unsigned)st * AT_KST;
        unsigned vb = sbase + AT_OV + (unsigned)st * AT_VST;
#pragma unroll
        for (int l = 0; l < 4; l++) {
            int f = tid + l * 256;
            int row = f >> 4, dc = (f & 15) * 8;
            unsigned so = (unsigned)(row * QP2 + dc) * 2u;
            size_t go = (size_t)(b * SEQ + kv0 + row) * KVDIM + kvh * 128 + dc;
            cpasync16(kb + so,          Kh + go);
            cpasync16(kb + 17408u + so, Kl + go);
        }
#pragma unroll
        for (int l = 0; l < 4; l++) {
            int f = tid + l * 256;
            int row = f >> 3, c = (f & 7) * 8;
            unsigned so = (unsigned)(row * VP2 + c) * 2u;
            size_t go = (size_t)(vz * 128 + row) * SEQ + kv0 + c;
            cpasync16(vb + so,          Vth + go);
            cpasync16(vb + 18432u + so, Vtl + go);
        }
    };

    float O[16][4];
#pragma unroll
    for (int i = 0; i < 16; i++)
#pragma unroll
        for (int v = 0; v < 4; v++) O[i][v] = 0.f;
    float m0 = -1e30f, m1 = -1e30f, l0 = 0.f, l1 = 0.f;

    const int nkv = (qt + 1) * 128;
    const int wrow = qt * 128 + w * 16;

    issue_kv(0, 0);
    cp_commit();

    for (int kv0 = 0, it = 0; kv0 < nkv; kv0 += 64, it ^= 1) {
        if (kv0 + 64 < nkv) { issue_kv(it ^ 1, kv0 + 64); cp_commit(); cp_wait1(); }
        else                { cp_wait0(); }
        __syncthreads();

        const unsigned bKh = sbase + AT_OK + (unsigned)it * AT_KST;
        const unsigned bKl = bKh + 17408u;
        const unsigned bVh = sbase + AT_OV + (unsigned)it * AT_VST;
        const unsigned bVl = bVh + 18432u;
        const unsigned bQh = sbase + AT_OQ;
        const unsigned bQl = sbase + AT_OQL;

        float S[8][4];
#pragma unroll
        for (int i = 0; i < 8; i++)
#pragma unroll
            for (int v = 0; v < 4; v++) S[i][v] = 0.f;
#pragma unroll
        for (int kc = 0; kc < 8; kc++) {
            unsigned qh[4], ql[4];
            ldsm4(qh[0], qh[1], qh[2], qh[3], addrA(bQh, lane, w * 16, kc * 16, QP2));
            ldsm4(ql[0], ql[1], ql[2], ql[3], addrA(bQl, lane, w * 16, kc * 16, QP2));
#pragma unroll
            for (int nn = 0; nn < 4; nn++) {
                unsigned kh[4], kl[4];
                ldsm4(kh[0], kh[1], kh[2], kh[3], addrB(bKh, lane, nn * 16, kc * 16, QP2));
                ldsm4(kl[0], kl[1], kl[2], kl[3], addrB(bKl, lane, nn * 16, kc * 16, QP2));
                mma_bf16(S[nn * 2], qh, kh[0], kh[1]);
                mma_bf16(S[nn * 2], qh, kl[0], kl[1]);
                mma_bf16(S[nn * 2], ql, kh[0], kh[1]);
                mma_bf16(S[nn * 2 + 1], qh, kh[2], kh[3]);
                mma_bf16(S[nn * 2 + 1], qh, kl[2], kl[3]);
                mma_bf16(S[nn * 2 + 1], ql, kh[2], kh[3]);
            }
        }

        const int r0g = wrow + (lane >> 2);
        const int r1g = r0g + 8;
        if (kv0 + 63 > wrow) {
#pragma unroll
            for (int nf = 0; nf < 8; nf++) {
                int c = kv0 + nf * 8 + (lane & 3) * 2;
                if (c > r0g) S[nf][0] = -1e30f;
                if (c + 1 > r0g) S[nf][1] = -1e30f;
                if (c > r1g) S[nf][2] = -1e30f;
                if (c + 1 > r1g) S[nf][3] = -1e30f;
            }
        }

        float t0 = -1e30f, t1 = -1e30f;
#pragma unroll
        for (int nf = 0; nf < 8; nf++) {
            t0 = fmaxf(t0, fmaxf(S[nf][0], S[nf][1]));
            t1 = fmaxf(t1, fmaxf(S[nf][2], S[nf][3]));
        }
        t0 = fmaxf(t0, __shfl_xor_sync(0xffffffffu, t0, 1));
        t0 = fmaxf(t0, __shfl_xor_sync(0xffffffffu, t0, 2));
        t1 = fmaxf(t1, __shfl_xor_sync(0xffffffffu, t1, 1));
        t1 = fmaxf(t1, __shfl_xor_sync(0xffffffffu, t1, 2));
        float mn0 = fmaxf(m0, t0), mn1 = fmaxf(m1, t1);
        float c0 = ex2f((m0 - mn0) * L), c1 = ex2f((m1 - mn1) * L);
        m0 = mn0; m1 = mn1;
        float rs0 = 0.f, rs1 = 0.f;
#pragma unroll
        for (int nf = 0; nf < 8; nf++) {
            S[nf][0] = ex2f((S[nf][0] - mn0) * L);
            S[nf][1] = ex2f((S[nf][1] - mn0) * L);
            S[nf][2] = ex2f((S[nf][2] - mn1) * L);
            S[nf][3] = ex2f((S[nf][3] - mn1) * L);
            rs0 += S[nf][0] + S[nf][1];
            rs1 += S[nf][2] + S[nf][3];
        }
        rs0 += __shfl_xor_sync(0xffffffffu, rs0, 1);
        rs0 += __shfl_xor_sync(0xffffffffu, rs0, 2);
        rs1 += __shfl_xor_sync(0xffffffffu, rs1, 1);
        rs1 += __shfl_xor_sync(0xffffffffu, rs1, 2);
        l0 = l0 * c0 + rs0;
        l1 = l1 * c1 + rs1;
#pragma unroll
        for (int i = 0; i < 16; i++) {
            O[i][0] *= c0; O[i][1] *= c0; O[i][2] *= c1; O[i][3] *= c1;
        }

#pragma unroll
        for (int kc = 0; kc < 4; kc++) {
            unsigned ah[4], al[4];
#pragma unroll
            for (int g = 0; g < 2; g++) {
                const float* s4 = S[kc * 2 + g];
                __nv_bfloat16 h0, l0b, h1, l1b, h2, l2b, h3, l3b;
                split_bf16(s4[0], h0, l0b); split_bf16(s4[1], h1, l1b);
                split_bf16(s4[2], h2, l2b); split_bf16(s4[3], h3, l3b);
                ah[g * 2]     = pack2(h0, h1); al[g * 2]     = pack2(l0b, l1b);
                ah[g * 2 + 1] = pack2(h2, h3); al[g * 2 + 1] = pack2(l2b, l3b);
            }
#pragma unroll
            for (int dn = 0; dn < 8; dn++) {
                unsigned vh[4], vl[4];
                ldsm4(vh[0], vh[1], vh[2], vh[3], addrB(bVh, lane, dn * 16, kc * 16, VP2));
                ldsm4(vl[0], vl[1], vl[2], vl[3], addrB(bVl, lane, dn * 16, kc * 16, VP2));
                mma_bf16(O[dn * 2], ah, vh[0], vh[1]);
                mma_bf16(O[dn * 2], ah, vl[0], vl[1]);
                mma_bf16(O[dn * 2], al, vh[0], vh[1]);
                mma_bf16(O[dn * 2 + 1], ah, vh[2], vh[3]);
                mma_bf16(O[dn * 2 + 1], ah, vl[2], vl[3]);
                mma_bf16(O[dn * 2 + 1], al, vh[2], vh[3]);
            }
        }
        __syncthreads();
    }

    float i0 = 1.f / l0, i1 = 1.f / l1;
    const int row0 = b * SEQ + wrow + (lane >> 2);
#pragma unroll
    for (int nf = 0; nf < 16; nf++) {
        int c = h * 128 + nf * 8 + (lane & 3) * 2;
        float a0 = O[nf][0] * i0, a1 = O[nf][1] * i0;
        float a2 = O[nf][2] * i1, a3 = O[nf][3] * i1;
        __nv_bfloat16 h0, l0b, h1, l1b, h2, l2b, h3, l3b;
        split_bf16(a0, h0, l0b); split_bf16(a1, h1, l1b);
        split_bf16(a2, h2, l2b); split_bf16(a3, h3, l3b);
        *(unsigned*)&Oh[(size_t)row0 * HIDDEN + c] = pack2(h0, h1);
        *(unsigned*)&Ol[(size_t)row0 * HIDDEN + c] = pack2(l0b, l1b);
        *(unsigned*)&Oh[(size_t)(row0 + 8) * HIDDEN + c] = pack2(h2, h3);
        *(unsigned*)&Ol[(size_t)(row0 + 8) * HIDDEN + c] = pack2(l2b, l3b);
    }
}

// ---------------------------------------------------------------------------
// Launch
// ---------------------------------------------------------------------------
extern "C" void kernel_launch(void* const* d_in, const int* in_sizes, int n_in,
                              void* d_out, int out_size)
{
    const float* hidden = (const float*)d_in[0];
    const int*   posids = (const int*)d_in[1];
    const float* Wq = (const float*)d_in[2];
    const float* bq = (const float*)d_in[3];
    const float* Wk = (const float*)d_in[4];
    const float* bk = (const float*)d_in[5];
    const float* Wv = (const float*)d_in[6];
    const float* bv = (const float*)d_in[7];
    const float* Wo = (const float*)d_in[8];
    const float* bo = (const float*)d_in[9];
    float* out = (float*)d_out;

    __nv_bfloat16 *Hh, *Hl, *Wqh, *Wql, *Wkh, *Wkl, *Wvh, *Wvl, *Woh, *Wol, *Ah, *Al;
    __nv_bfloat16 *Qh, *Ql, *Kh, *Kl, *Vth, *Vtl;
    float *qf, *kf, *vf;
    cudaGetSymbolAddress((void**)&Hh, g_Hh);   cudaGetSymbolAddress((void**)&Hl, g_Hl);
    cudaGetSymbolAddress((void**)&Wqh, g_Wqt_h); cudaGetSymbolAddress((void**)&Wql, g_Wqt_l);
    cudaGetSymbolAddress((void**)&Wkh, g_Wkt_h); cudaGetSymbolAddress((void**)&Wkl, g_Wkt_l);
    cudaGetSymbolAddress((void**)&Wvh, g_Wvt_h); cudaGetSymbolAddress((void**)&Wvl, g_Wvt_l);
    cudaGetSymbolAddress((void**)&Woh, g_Wot_h); cudaGetSymbolAddress((void**)&Wol, g_Wot_l);
    cudaGetSymbolAddress((void**)&Ah, g_Ah);   cudaGetSymbolAddress((void**)&Al, g_Al);
    cudaGetSymbolAddress((void**)&Qh, g_Qh);   cudaGetSymbolAddress((void**)&Ql, g_Ql);
    cudaGetSymbolAddress((void**)&Kh, g_Kh);   cudaGetSymbolAddress((void**)&Kl, g_Kl);
    cudaGetSymbolAddress((void**)&Vth, g_Vth); cudaGetSymbolAddress((void**)&Vtl, g_Vtl);
    cudaGetSymbolAddress((void**)&qf, g_qf);   cudaGetSymbolAddress((void**)&kf, g_kf);
    cudaGetSymbolAddress((void**)&vf, g_vf);

    // idx 0: split hidden
    split_f32<<<(MROWS * HIDDEN / 4 + 255) / 256, 256>>>(hidden, Hh, Hl, MROWS * HIDDEN / 4);
    // idx 1: all weight transposes in one launch
    transpose_all<<<dim3(HIDDEN / 32, HIDDEN / 32, 4), dim3(32, 8)>>>(
        Wq, Wk, Wv, Wo, Wqh, Wql, Wkh, Wkl, Wvh, Wvl, Woh, Wol);

    // idx 2: merged Q/K/V projection (wave-packed)
    cudaFuncSetAttribute(gemm_qkv, cudaFuncAttributeMaxDynamicSharedMemorySize, GEMM_SMEM);
    cudaFuncSetAttribute(gemm_bf16x3, cudaFuncAttributeMaxDynamicSharedMemorySize, GEMM_SMEM);
    gemm_qkv<<<dim3(24, MROWS / 128), 256, GEMM_SMEM>>>(
        Hh, Hl, Wqh, Wql, Wkh, Wkl, Wvh, Wvl, bq, bk, bv, qf, kf, vf);

    // idx 3: merged RoPE-split + V-transpose-split (one launch)
    prep_rope_vt<<<MROWS / 2 + 2048, 256>>>(posids, qf, kf, vf, Qh, Ql, Kh, Kl, Vth, Vtl);

    // idx 4: attention — LPT grid: x = (h,b), y = qt slot (longest first)
    cudaFuncSetAttribute(attn_mma, cudaFuncAttributeMaxDynamicSharedMemorySize, ATTN_SMEM);
    attn_mma<<<dim3(NHEADS * BATCH, SEQ / 128), 256, ATTN_SMEM>>>(Qh, Ql, Kh, Kl, Vth, Vtl, Ah, Al);

    // idx 5: output projection
    gemm_bf16x3<<<dim3(HIDDEN / 128, MROWS / 128), 256, GEMM_SMEM>>>(Ah, Al, Woh, Wol, bo, out, MROWS, HIDDEN, HIDDEN);
}

// round 17
// speedup vs baseline: 1.1490x; 1.0069x over previous
#include <cuda_runtime.h>
#include <cuda_bf16.h>
#include <math.h>
#include <stdint.h>

#define HIDDEN   2048
#define NHEADS   16
#define NKVHEADS 4
#define HEADDIM  128
#define BATCH    2
#define SEQ      2048
#define MROWS    (BATCH * SEQ)          // 4096
#define KVDIM    (NKVHEADS * HEADDIM)   // 512

#define DEVINL __device__ __forceinline__

// ---------------------------------------------------------------------------
// Scratch
// ---------------------------------------------------------------------------
__device__ __nv_bfloat16 g_Hh[MROWS * HIDDEN], g_Hl[MROWS * HIDDEN];
__device__ __nv_bfloat16 g_Wqt_h[HIDDEN * HIDDEN], g_Wqt_l[HIDDEN * HIDDEN];
__device__ __nv_bfloat16 g_Wkt_h[KVDIM * HIDDEN],  g_Wkt_l[KVDIM * HIDDEN];
__device__ __nv_bfloat16 g_Wvt_h[KVDIM * HIDDEN],  g_Wvt_l[KVDIM * HIDDEN];
__device__ __nv_bfloat16 g_Wot_h[HIDDEN * HIDDEN], g_Wot_l[HIDDEN * HIDDEN];
__device__ float g_qf[MROWS * HIDDEN];
__device__ float g_kf[MROWS * KVDIM];
__device__ float g_vf[MROWS * KVDIM];
__device__ __nv_bfloat16 g_Ah[MROWS * HIDDEN], g_Al[MROWS * HIDDEN];
__device__ __nv_bfloat16 g_Qh[MROWS * HIDDEN], g_Ql[MROWS * HIDDEN];
__device__ __nv_bfloat16 g_Kh[MROWS * KVDIM],  g_Kl[MROWS * KVDIM];
__device__ __nv_bfloat16 g_Vth[BATCH * KVDIM * SEQ], g_Vtl[BATCH * KVDIM * SEQ]; // [z*128+d][s]

// ---------------------------------------------------------------------------
// PTX helpers
// ---------------------------------------------------------------------------
DEVINL unsigned smem_u32(const void* p) { return (unsigned)__cvta_generic_to_shared(p); }

DEVINL void ldsm4(unsigned& r0, unsigned& r1, unsigned& r2, unsigned& r3, unsigned a) {
    asm volatile("ldmatrix.sync.aligned.m8n8.x4.shared.b16 {%0,%1,%2,%3}, [%4];\n"
                 : "=r"(r0), "=r"(r1), "=r"(r2), "=r"(r3) : "r"(a));
}
DEVINL void mma_bf16(float c[4], const unsigned a[4], unsigned b0, unsigned b1) {
    asm volatile(
        "mma.sync.aligned.m16n8k16.row.col.f32.bf16.bf16.f32 "
        "{%0,%1,%2,%3}, {%4,%5,%6,%7}, {%8,%9}, {%0,%1,%2,%3};\n"
        : "+f"(c[0]), "+f"(c[1]), "+f"(c[2]), "+f"(c[3])
        : "r"(a[0]), "r"(a[1]), "r"(a[2]), "r"(a[3]), "r"(b0), "r"(b1));
}
DEVINL unsigned addrA(unsigned base, int lane, int row0, int col0, int pitch) {
    int r = row0 + (lane & 15);
    int c = col0 + ((lane >> 4) << 3);
    return base + (unsigned)(r * pitch + c) * 2u;
}
DEVINL unsigned addrB(unsigned base, int lane, int row0, int col0, int pitch) {
    int r = row0 + ((lane >> 4) << 3) + (lane & 7);
    int c = col0 + (((lane >> 3) & 1) << 3);
    return base + (unsigned)(r * pitch + c) * 2u;
}
DEVINL float ex2f(float x) { float r; asm("ex2.approx.ftz.f32 %0, %1;" : "=f"(r) : "f"(x)); return r; }

DEVINL void cpasync16(unsigned dst, const void* src) {
    asm volatile("cp.async.cg.shared.global [%0], [%1], 16;\n" :: "r"(dst), "l"(src));
}
DEVINL void cp_commit() { asm volatile("cp.async.commit_group;\n" ::); }
DEVINL void cp_wait0()  { asm volatile("cp.async.wait_group 0;\n" ::); }
DEVINL void cp_wait1()  { asm volatile("cp.async.wait_group 1;\n" ::); }

DEVINL void split_bf16(float x, __nv_bfloat16& h, __nv_bfloat16& l) {
    h = __float2bfloat16(x);
    l = __float2bfloat16(x - __bfloat162float(h));
}
DEVINL unsigned pack2(__nv_bfloat16 lo, __nv_bfloat16 hi) {
    return (unsigned)__bfloat16_as_ushort(lo) | ((unsigned)__bfloat16_as_ushort(hi) << 16);
}

// ---------------------------------------------------------------------------
// Weight transposes (z=0..3) + hidden split (z=4) in ONE launch.
// grid (64, 64, 5), block (32, 8).
// ---------------------------------------------------------------------------
__global__ void transpose_all(
    const float* __restrict__ Wq, const float* __restrict__ Wk,
    const float* __restrict__ Wv, const float* __restrict__ Wo,
    const float* __restrict__ hidden,
    __nv_bfloat16* __restrict__ Wqh, __nv_bfloat16* __restrict__ Wql,
    __nv_bfloat16* __restrict__ Wkh, __nv_bfloat16* __restrict__ Wkl,
    __nv_bfloat16* __restrict__ Wvh, __nv_bfloat16* __restrict__ Wvl,
    __nv_bfloat16* __restrict__ Woh, __nv_bfloat16* __restrict__ Wol,
    __nv_bfloat16* __restrict__ Hh,  __nv_bfloat16* __restrict__ Hl)
{
    const int z = blockIdx.z;
    const int tid = threadIdx.y * 32 + threadIdx.x;

    if (z == 4) {
        // hidden fp32 -> bf16 hi/lo split: 4096 blocks x 256 thr x 2 float4
        int bid = blockIdx.y * 64 + blockIdx.x;
        size_t base = (size_t)bid * 512 + tid;
#pragma unroll
        for (int r = 0; r < 2; r++) {
            size_t i = base + r * 256;
            float4 v = ((const float4*)hidden)[i];
            __nv_bfloat16 h0, h1, h2, h3, l0, l1, l2, l3;
            split_bf16(v.x, h0, l0); split_bf16(v.y, h1, l1);
            split_bf16(v.z, h2, l2); split_bf16(v.w, h3, l3);
            *(uint2*)(Hh + i * 4) = make_uint2(pack2(h0, h1), pack2(h2, h3));
            *(uint2*)(Hl + i * 4) = make_uint2(pack2(l0, l1), pack2(l2, l3));
        }
        return;
    }

    const float* W; __nv_bfloat16 *Th, *Tl; int N;
    if (z == 0)      { W = Wq; Th = Wqh; Tl = Wql; N = HIDDEN; }
    else if (z == 1) { W = Wk; Th = Wkh; Tl = Wkl; N = KVDIM; }
    else if (z == 2) { W = Wv; Th = Wvh; Tl = Wvl; N = KVDIM; }
    else             { W = Wo; Th = Woh; Tl = Wol; N = HIDDEN; }

    int n0 = blockIdx.x * 32, k0 = blockIdx.y * 32;
    if (n0 >= N) return;

    __shared__ float t[32][33];
    int tx = threadIdx.x, ty = threadIdx.y;
#pragma unroll
    for (int i = 0; i < 4; i++)
        t[ty + i * 8][tx] = W[(size_t)(k0 + ty + i * 8) * N + n0 + tx];
    __syncthreads();
#pragma unroll
    for (int i = 0; i < 4; i++) {
        float v = t[tx][ty + i * 8];
        __nv_bfloat16 h, l;
        split_bf16(v, h, l);
        size_t o = (size_t)(n0 + ty + i * 8) * HIDDEN + k0 + tx;
        Th[o] = h; Tl[o] = l;
    }
}

// ---------------------------------------------------------------------------
// Merged RoPE-split (blocks 0..2047) + V-transpose-split (blocks 2048..4095)
// ---------------------------------------------------------------------------
__global__ __launch_bounds__(256) void prep_rope_vt(
    const int* __restrict__ pos_ids,
    const float* __restrict__ qf, const float* __restrict__ kf,
    const float* __restrict__ vf,
    __nv_bfloat16* __restrict__ Qh, __nv_bfloat16* __restrict__ Ql,
    __nv_bfloat16* __restrict__ Kh, __nv_bfloat16* __restrict__ Kl,
    __nv_bfloat16* __restrict__ Vth, __nv_bfloat16* __restrict__ Vtl)
{
    __shared__ float cs[2][64], sn[2][64];
    __shared__ float tt[32][33];

    const int bx = blockIdx.x;
    const int tid = threadIdx.x;

    if (bx < MROWS / 2) {
        const int half = tid >> 7;
        const int ht = tid & 127;
        const int bs = bx * 2 + half;
        if (ht < 64) {
            double pos = (double)pos_ids[bs];
            double inv = exp(-((double)ht / 64.0) * 13.815510557964274);
            double phi = pos * inv;
            float phi_hi = (float)phi;
            float phi_lo = (float)(phi - (double)phi_hi);
            float sh, ch;
            sincosf(phi_hi, &sh, &ch);
            sn[half][ht] = sh + ch * phi_lo;
            cs[half][ht] = ch - sh * phi_lo;
        }
        __syncthreads();

        const float* q = qf + (size_t)bs * HIDDEN;
#pragma unroll
        for (int p = ht; p < NHEADS * 32; p += 128) {
            int h = p >> 5, d = (p & 31) * 2;
            size_t base = (size_t)bs * HIDDEN + h * HEADDIM;
            float2 x0 = *(const float2*)(q + h * HEADDIM + d);
            float2 x1 = *(const float2*)(q + h * HEADDIM + d + 64);
            float c0 = cs[half][d], c1 = cs[half][d + 1];
            float s0 = sn[half][d], s1 = sn[half][d + 1];
            float ya0 = x0.x * c0 - x1.x * s0, ya1 = x0.y * c1 - x1.y * s1;
            float yb0 = x1.x * c0 + x0.x * s0, yb1 = x1.y * c1 + x0.y * s1;
            __nv_bfloat16 ha0, la0, ha1, la1, hb0, lb0, hb1, lb1;
            split_bf16(ya0, ha0, la0); split_bf16(ya1, ha1, la1);
            split_bf16(yb0, hb0, lb0); split_bf16(yb1, hb1, lb1);
            *(unsigned*)&Qh[base + d]      = pack2(ha0, ha1);
            *(unsigned*)&Ql[base + d]      = pack2(la0, la1);
            *(unsigned*)&Qh[base + d + 64] = pack2(hb0, hb1);
            *(unsigned*)&Ql[base + d + 64] = pack2(lb0, lb1);
        }
        const float* k = kf + (size_t)bs * KVDIM;
#pragma unroll
        for (int p = ht; p < NKVHEADS * 32; p += 128) {
            int h = p >> 5, d = (p & 31) * 2;
            size_t base = (size_t)bs * KVDIM + h * HEADDIM;
            float2 x0 = *(const float2*)(k + h * HEADDIM + d);
            float2 x1 = *(const float2*)(k + h * HEADDIM + d + 64);
            float c0 = cs[half][d], c1 = cs[half][d + 1];
            float s0 = sn[half][d], s1 = sn[half][d + 1];
            float ya0 = x0.x * c0 - x1.x * s0, ya1 = x0.y * c1 - x1.y * s1;
            float yb0 = x1.x * c0 + x0.x * s0, yb1 = x1.y * c1 + x0.y * s1;
            __nv_bfloat16 ha0, la0, ha1, la1, hb0, lb0, hb1, lb1;
            split_bf16(ya0, ha0, la0); split_bf16(ya1, ha1, la1);
            split_bf16(yb0, hb0, lb0); split_bf16(yb1, hb1, lb1);
            *(unsigned*)&Kh[base + d]      = pack2(ha0, ha1);
            *(unsigned*)&Kl[base + d]      = pack2(la0, la1);
            *(unsigned*)&Kh[base + d + 64] = pack2(hb0, hb1);
            *(unsigned*)&Kl[base + d + 64] = pack2(lb0, lb1);
        }
    } else {
        int vi = bx - MROWS / 2;
        int s0 = (vi & 63) * 32;
        int d0 = ((vi >> 6) & 3) * 32;
        int z = vi >> 8;
        int b = z >> 2, kvh = z & 3;
        int tx = tid & 31, ty = tid >> 5;
#pragma unroll
        for (int i = 0; i < 4; i++)
            tt[ty + i * 8][tx] =
                vf[(size_t)(b * SEQ + s0 + ty + i * 8) * KVDIM + kvh * 128 + d0 + tx];
        __syncthreads();
#pragma unroll
        for (int i = 0; i < 4; i++) {
            float v = tt[tx][ty + i * 8];
            __nv_bfloat16 h, l;
            split_bf16(v, h, l);
            size_t o = (size_t)(z * 128 + d0 + ty + i * 8) * SEQ + s0 + tx;
            Vth[o] = h; Vtl[o] = l;
        }
    }
}

// ---------------------------------------------------------------------------
// GEMM core (validated): one 128x128 tile of C = (Ah+Al)@(Bh+Bl)^T + bias
// ---------------------------------------------------------------------------
#define KP 40
#define GEMM_TILE_B  (128 * KP * 2)
#define GEMM_STAGE_B (4 * GEMM_TILE_B)
#define GEMM_SMEM    (2 * GEMM_STAGE_B)          // 81920

DEVINL void gemm_tile(
    const __nv_bfloat16* Ah, const __nv_bfloat16* Al,
    const __nv_bfloat16* Bh, const __nv_bfloat16* Bl,
    const float* bias, float* C,
    int m0, int n0loc, int N, int K, char* gsm)
{
    const unsigned sbase = smem_u32(gsm);
    const int tid = threadIdx.x, lane = tid & 31, warp = tid >> 5;
    const int wm = warp >> 2, wn = warp & 3;

    float acc[4][4][4];
#pragma unroll
    for (int i = 0; i < 4; i++)
#pragma unroll
        for (int j = 0; j < 4; j++)
#pragma unroll
            for (int v = 0; v < 4; v++) acc[i][j][v] = 0.f;

    const int nk = K / 32;

    auto issue = [&](int st, int k0) {
        unsigned sb = sbase + (unsigned)st * GEMM_STAGE_B;
#pragma unroll
        for (int l = 0; l < 2; l++) {
            int f = tid + l * 256;
            int row = f >> 2;
            int kc = (f & 3) * 8;
            unsigned so = (unsigned)(row * KP + kc) * 2u;
            size_t goA = (size_t)(m0 + row) * K + k0 + kc;
            size_t goB = (size_t)(n0loc + row) * K + k0 + kc;
            cpasync16(sb + so,                     Ah + goA);
            cpasync16(sb + GEMM_TILE_B + so,       Al + goA);
            cpasync16(sb + 2 * GEMM_TILE_B + so,   Bh + goB);
            cpasync16(sb + 3 * GEMM_TILE_B + so,   Bl + goB);
        }
    };

    issue(0, 0);
    cp_commit();

    for (int kt = 0; kt < nk; kt++) {
        int st = kt & 1;
        if (kt + 1 < nk) { issue(st ^ 1, (kt + 1) * 32); cp_commit(); cp_wait1(); }
        else             { cp_wait0(); }
        __syncthreads();

        unsigned sb  = sbase + (unsigned)st * GEMM_STAGE_B;
        unsigned bAh = sb;
        unsigned bAl = sb + GEMM_TILE_B;
        unsigned bBh = sb + 2 * GEMM_TILE_B;
        unsigned bBl = sb + 3 * GEMM_TILE_B;

#pragma unroll
        for (int ks = 0; ks < 2; ks++) {
            int kb = ks * 16;
            unsigned bh[4][2], bl[4][2];
#pragma unroll
            for (int g = 0; g < 2; g++) {
                unsigned r0, r1, r2, r3;
                ldsm4(r0, r1, r2, r3, addrB(bBh, lane, wn * 32 + g * 16, kb, KP));
                bh[g * 2][0] = r0; bh[g * 2][1] = r1;
                bh[g * 2 + 1][0] = r2; bh[g * 2 + 1][1] = r3;
                ldsm4(r0, r1, r2, r3, addrB(bBl, lane, wn * 32 + g * 16, kb, KP));
                bl[g * 2][0] = r0; bl[g * 2][1] = r1;
                bl[g * 2 + 1][0] = r2; bl[g * 2 + 1][1] = r3;
            }
#pragma unroll
            for (int mf = 0; mf < 4; mf++) {
                unsigned ah[4], al[4];
                ldsm4(ah[0], ah[1], ah[2], ah[3], addrA(bAh, lane, wm * 64 + mf * 16, kb, KP));
                ldsm4(al[0], al[1], al[2], al[3], addrA(bAl, lane, wm * 64 + mf * 16, kb, KP));
#pragma unroll
                for (int nf = 0; nf < 4; nf++) {
                    mma_bf16(acc[mf][nf], ah, bh[nf][0], bh[nf][1]);
                    mma_bf16(acc[mf][nf], ah, bl[nf][0], bl[nf][1]);
                    mma_bf16(acc[mf][nf], al, bh[nf][0], bh[nf][1]);
                }
            }
        }
        __syncthreads();
    }

    const int rb = m0 + wm * 64, cb = n0loc + wn * 32;
#pragma unroll
    for (int mf = 0; mf < 4; mf++)
#pragma unroll
        for (int nf = 0; nf < 4; nf++) {
            int r = rb + mf * 16 + (lane >> 2);
            int c = cb + nf * 8 + (lane & 3) * 2;
            float b0 = bias[c], b1 = bias[c + 1];
            *(float2*)&C[(size_t)r * N + c] =
                make_float2(acc[mf][nf][0] + b0, acc[mf][nf][1] + b1);
            *(float2*)&C[(size_t)(r + 8) * N + c] =
                make_float2(acc[mf][nf][2] + b0, acc[mf][nf][3] + b1);
        }
}

// Merged Q/K/V projection: one launch, grid (24, 32).
__global__ __launch_bounds__(256) void gemm_qkv(
    const __nv_bfloat16* __restrict__ Ah, const __nv_bfloat16* __restrict__ Al,
    const __nv_bfloat16* __restrict__ Wqh, const __nv_bfloat16* __restrict__ Wql,
    const __nv_bfloat16* __restrict__ Wkh, const __nv_bfloat16* __restrict__ Wkl,
    const __nv_bfloat16* __restrict__ Wvh, const __nv_bfloat16* __restrict__ Wvl,
    const float* __restrict__ bq, const float* __restrict__ bk, const float* __restrict__ bv,
    float* __restrict__ qf, float* __restrict__ kf, float* __restrict__ vf)
{
    extern __shared__ char gsm[];
    const int nt = blockIdx.x;
    const int m0 = blockIdx.y * 128;
    const __nv_bfloat16 *Bh, *Bl; const float* bias; float* C; int N, n0;
    if (nt < 16)      { Bh = Wqh; Bl = Wql; bias = bq; C = qf; N = HIDDEN; n0 = nt * 128; }
    else if (nt < 20) { Bh = Wkh; Bl = Wkl; bias = bk; C = kf; N = KVDIM;  n0 = (nt - 16) * 128; }
    else              { Bh = Wvh; Bl = Wvl; bias = bv; C = vf; N = KVDIM;  n0 = (nt - 20) * 128; }
    gemm_tile(Ah, Al, Bh, Bl, bias, C, m0, n0, N, HIDDEN, gsm);
}

__global__ __launch_bounds__(256) void gemm_bf16x3(
    const __nv_bfloat16* __restrict__ Ah, const __nv_bfloat16* __restrict__ Al,
    const __nv_bfloat16* __restrict__ Bh, const __nv_bfloat16* __restrict__ Bl,
    const float* __restrict__ bias, float* __restrict__ C,
    int M, int N, int K)
{
    extern __shared__ char gsm[];
    gemm_tile(Ah, Al, Bh, Bl, bias, C, blockIdx.y * 128, blockIdx.x * 128, N, K, gsm);
}

// ---------------------------------------------------------------------------
// Tensor-core causal flash attention (bf16x3), 2-stage cp.async K/V pipeline.
// LPT dispatch; Q fragments hoisted out of the kv loop (loop-invariant).
// ---------------------------------------------------------------------------
#define QP2 136
#define VP2 72
#define AT_OQ  0u
#define AT_OQL 34816u
#define AT_OK  69632u
#define AT_KST 34816u
#define AT_OV  139264u
#define AT_VST 36864u
#define ATTN_SMEM 212992

__global__ __launch_bounds__(256) void attn_mma(
    const __nv_bfloat16* __restrict__ Qh, const __nv_bfloat16* __restrict__ Ql,
    const __nv_bfloat16* __restrict__ Kh, const __nv_bfloat16* __restrict__ Kl,
    const __nv_bfloat16* __restrict__ Vth, const __nv_bfloat16* __restrict__ Vtl,
    __nv_bfloat16* __restrict__ Oh, __nv_bfloat16* __restrict__ Ol)
{
    extern __shared__ __nv_bfloat16 sm[];
    const unsigned sbase = smem_u32(sm);

    const int tid = threadIdx.x, lane = tid & 31, w = tid >> 5;
    const int h = blockIdx.x & 15, b = blockIdx.x >> 4;
    const int qt = (int)(gridDim.y - 1) - (int)blockIdx.y;
    const int kvh = h >> 2;
    const int vz = b * NKVHEADS + kvh;
    const float L = 0.08838834764831845f * 1.4426950408889634f;

    __nv_bfloat16* sQh = sm;
    __nv_bfloat16* sQl = sm + 128 * QP2;
#pragma unroll
    for (int l = 0; l < 8; l++) {
        int f = tid + l * 256;
        int row = f >> 4, dc = (f & 15) * 8;
        size_t go = (size_t)(b * SEQ + qt * 128 + row) * HIDDEN + h * 128 + dc;
        *(uint4*)&sQh[row * QP2 + dc] = *(const uint4*)(Qh + go);
        *(uint4*)&sQl[row * QP2 + dc] = *(const uint4*)(Ql + go);
    }

    auto issue_kv = [&](int st, int kv0) {
        unsigned kb = sbase + AT_OK + (unsigned)st * AT_KST;
        unsigned vb = sbase + AT_OV + (unsigned)st * AT_VST;
#pragma unroll
        for (int l = 0; l < 4; l++) {
            int f = tid + l * 256;
            int row = f >> 4, dc = (f & 15) * 8;
            unsigned so = (unsigned)(row * QP2 + dc) * 2u;
            size_t go = (size_t)(b * SEQ + kv0 + row) * KVDIM + kvh * 128 + dc;
            cpasync16(kb + so,          Kh + go);
            cpasync16(kb + 17408u + so, Kl + go);
        }
#pragma unroll
        for (int l = 0; l < 4; l++) {
            int f = tid + l * 256;
            int row = f >> 3, c = (f & 7) * 8;
            unsigned so = (unsigned)(row * VP2 + c) * 2u;
            size_t go = (size_t)(vz * 128 + row) * SEQ + kv0 + c;
            cpasync16(vb + so,          Vth + go);
            cpasync16(vb + 18432u + so, Vtl + go);
        }
    };

    issue_kv(0, 0);
    cp_commit();

    // Hoist Q fragments (loop-invariant): 8 kc x (hi, lo)
    __syncthreads();
    unsigned qfh[8][4], qfl[8][4];
#pragma unroll
    for (int kc = 0; kc < 8; kc++) {
        ldsm4(qfh[kc][0], qfh[kc][1], qfh[kc][2], qfh[kc][3],
              addrA(sbase + AT_OQ, lane, w * 16, kc * 16, QP2));
        ldsm4(qfl[kc][0], qfl[kc][1], qfl[kc][2], qfl[kc][3],
              addrA(sbase + AT_OQL, lane, w * 16, kc * 16, QP2));
    }

    float O[16][4];
#pragma unroll
    for (int i = 0; i < 16; i++)
#pragma unroll
        for (int v = 0; v < 4; v++) O[i][v] = 0.f;
    float m0 = -1e30f, m1 = -1e30f, l0 = 0.f, l1 = 0.f;

    const int nkv = (qt + 1) * 128;
    const int wrow = qt * 128 + w * 16;

    for (int kv0 = 0, it = 0; kv0 < nkv; kv0 += 64, it ^= 1) {
        if (kv0 + 64 < nkv) { issue_kv(it ^ 1, kv0 + 64); cp_commit(); cp_wait1(); }
        else                { cp_wait0(); }
        __syncthreads();

        const unsigned bKh = sbase + AT_OK + (unsigned)it * AT_KST;
        const unsigned bKl = bKh + 17408u;
        const unsigned bVh = sbase + AT_OV + (unsigned)it * AT_VST;
        const unsigned bVl = bVh + 18432u;

        float S[8][4];
#pragma unroll
        for (int i = 0; i < 8; i++)
#pragma unroll
            for (int v = 0; v < 4; v++) S[i][v] = 0.f;
#pragma unroll
        for (int kc = 0; kc < 8; kc++) {
#pragma unroll
            for (int nn = 0; nn < 4; nn++) {
                unsigned kh[4], kl[4];
                ldsm4(kh[0], kh[1], kh[2], kh[3], addrB(bKh, lane, nn * 16, kc * 16, QP2));
                ldsm4(kl[0], kl[1], kl[2], kl[3], addrB(bKl, lane, nn * 16, kc * 16, QP2));
                mma_bf16(S[nn * 2], qfh[kc], kh[0], kh[1]);
                mma_bf16(S[nn * 2], qfh[kc], kl[0], kl[1]);
                mma_bf16(S[nn * 2], qfl[kc], kh[0], kh[1]);
                mma_bf16(S[nn * 2 + 1], qfh[kc], kh[2], kh[3]);
                mma_bf16(S[nn * 2 + 1], qfh[kc], kl[2], kl[3]);
                mma_bf16(S[nn * 2 + 1], qfl[kc], kh[2], kh[3]);
            }
        }

        const int r0g = wrow + (lane >> 2);
        const int r1g = r0g + 8;
        if (kv0 + 63 > wrow) {
#pragma unroll
            for (int nf = 0; nf < 8; nf++) {
                int c = kv0 + nf * 8 + (lane & 3) * 2;
                if (c > r0g) S[nf][0] = -1e30f;
                if (c + 1 > r0g) S[nf][1] = -1e30f;
                if (c > r1g) S[nf][2] = -1e30f;
                if (c + 1 > r1g) S[nf][3] = -1e30f;
            }
        }

        float t0 = -1e30f, t1 = -1e30f;
#pragma unroll
        for (int nf = 0; nf < 8; nf++) {
            t0 = fmaxf(t0, fmaxf(S[nf][0], S[nf][1]));
            t1 = fmaxf(t1, fmaxf(S[nf][2], S[nf][3]));
        }
        t0 = fmaxf(t0, __shfl_xor_sync(0xffffffffu, t0, 1));
        t0 = fmaxf(t0, __shfl_xor_sync(0xffffffffu, t0, 2));
        t1 = fmaxf(t1, __shfl_xor_sync(0xffffffffu, t1, 1));
        t1 = fmaxf(t1, __shfl_xor_sync(0xffffffffu, t1, 2));
        float mn0 = fmaxf(m0, t0), mn1 = fmaxf(m1, t1);
        float c0 = ex2f((m0 - mn0) * L), c1 = ex2f((m1 - mn1) * L);
        m0 = mn0; m1 = mn1;
        float rs0 = 0.f, rs1 = 0.f;
#pragma unroll
        for (int nf = 0; nf < 8; nf++) {
            S[nf][0] = ex2f((S[nf][0] - mn0) * L);
            S[nf][1] = ex2f((S[nf][1] - mn0) * L);
            S[nf][2] = ex2f((S[nf][2] - mn1) * L);
            S[nf][3] = ex2f((S[nf][3] - mn1) * L);
            rs0 += S[nf][0] + S[nf][1];
            rs1 += S[nf][2] + S[nf][3];
        }
        rs0 += __shfl_xor_sync(0xffffffffu, rs0, 1);
        rs0 += __shfl_xor_sync(0xffffffffu, rs0, 2);
        rs1 += __shfl_xor_sync(0xffffffffu, rs1, 1);
        rs1 += __shfl_xor_sync(0xffffffffu, rs1, 2);
        l0 = l0 * c0 + rs0;
        l1 = l1 * c1 + rs1;
#pragma unroll
        for (int i = 0; i < 16; i++) {
            O[i][0] *= c0; O[i][1] *= c0; O[i][2] *= c1; O[i][3] *= c1;
        }

#pragma unroll
        for (int kc = 0; kc < 4; kc++) {
            unsigned ah[4], al[4];
#pragma unroll
            for (int g = 0; g < 2; g++) {
                const float* s4 = S[kc * 2 + g];
                __nv_bfloat16 h0, l0b, h1, l1b, h2, l2b, h3, l3b;
                split_bf16(s4[0], h0, l0b); split_bf16(s4[1], h1, l1b);
                split_bf16(s4[2], h2, l2b); split_bf16(s4[3], h3, l3b);
                ah[g * 2]     = pack2(h0, h1); al[g * 2]     = pack2(l0b, l1b);
                ah[g * 2 + 1] = pack2(h2, h3); al[g * 2 + 1] = pack2(l2b, l3b);
            }
#pragma unroll
            for (int dn = 0; dn < 8; dn++) {
                unsigned vh[4], vl[4];
                ldsm4(vh[0], vh[1], vh[2], vh[3], addrB(bVh, lane, dn * 16, kc * 16, VP2));
                ldsm4(vl[0], vl[1], vl[2], vl[3], addrB(bVl, lane, dn * 16, kc * 16, VP2));
                mma_bf16(O[dn * 2], ah, vh[0], vh[1]);
                mma_bf16(O[dn * 2], ah, vl[0], vl[1]);
                mma_bf16(O[dn * 2], al, vh[0], vh[1]);
                mma_bf16(O[dn * 2 + 1], ah, vh[2], vh[3]);
                mma_bf16(O[dn * 2 + 1], ah, vl[2], vl[3]);
                mma_bf16(O[dn * 2 + 1], al, vh[2], vh[3]);
            }
        }
        __syncthreads();
    }

    float i0 = 1.f / l0, i1 = 1.f / l1;
    const int row0 = b * SEQ + wrow + (lane >> 2);
#pragma unroll
    for (int nf = 0; nf < 16; nf++) {
        int c = h * 128 + nf * 8 + (lane & 3) * 2;
        float a0 = O[nf][0] * i0, a1 = O[nf][1] * i0;
        float a2 = O[nf][2] * i1, a3 = O[nf][3] * i1;
        __nv_bfloat16 h0, l0b, h1, l1b, h2, l2b, h3, l3b;
        split_bf16(a0, h0, l0b); split_bf16(a1, h1, l1b);
        split_bf16(a2, h2, l2b); split_bf16(a3, h3, l3b);
        *(unsigned*)&Oh[(size_t)row0 * HIDDEN + c] = pack2(h0, h1);
        *(unsigned*)&Ol[(size_t)row0 * HIDDEN + c] = pack2(l0b, l1b);
        *(unsigned*)&Oh[(size_t)(row0 + 8) * HIDDEN + c] = pack2(h2, h3);
        *(unsigned*)&Ol[(size_t)(row0 + 8) * HIDDEN + c] = pack2(l2b, l3b);
    }
}

// ---------------------------------------------------------------------------
// Launch
// ---------------------------------------------------------------------------
extern "C" void kernel_launch(void* const* d_in, const int* in_sizes, int n_in,
                              void* d_out, int out_size)
{
    const float* hidden = (const float*)d_in[0];
    const int*   posids = (const int*)d_in[1];
    const float* Wq = (const float*)d_in[2];
    const float* bq = (const float*)d_in[3];
    const float* Wk = (const float*)d_in[4];
    const float* bk = (const float*)d_in[5];
    const float* Wv = (const float*)d_in[6];
    const float* bv = (const float*)d_in[7];
    const float* Wo = (const float*)d_in[8];
    const float* bo = (const float*)d_in[9];
    float* out = (float*)d_out;

    __nv_bfloat16 *Hh, *Hl, *Wqh, *Wql, *Wkh, *Wkl, *Wvh, *Wvl, *Woh, *Wol, *Ah, *Al;
    __nv_bfloat16 *Qh, *Ql, *Kh, *Kl, *Vth, *Vtl;
    float *qf, *kf, *vf;
    cudaGetSymbolAddress((void**)&Hh, g_Hh);   cudaGetSymbolAddress((void**)&Hl, g_Hl);
    cudaGetSymbolAddress((void**)&Wqh, g_Wqt_h); cudaGetSymbolAddress((void**)&Wql, g_Wqt_l);
    cudaGetSymbolAddress((void**)&Wkh, g_Wkt_h); cudaGetSymbolAddress((void**)&Wkl, g_Wkt_l);
    cudaGetSymbolAddress((void**)&Wvh, g_Wvt_h); cudaGetSymbolAddress((void**)&Wvl, g_Wvt_l);
    cudaGetSymbolAddress((void**)&Woh, g_Wot_h); cudaGetSymbolAddress((void**)&Wol, g_Wot_l);
    cudaGetSymbolAddress((void**)&Ah, g_Ah);   cudaGetSymbolAddress((void**)&Al, g_Al);
    cudaGetSymbolAddress((void**)&Qh, g_Qh);   cudaGetSymbolAddress((void**)&Ql, g_Ql);
    cudaGetSymbolAddress((void**)&Kh, g_Kh);   cudaGetSymbolAddress((void**)&Kl, g_Kl);
    cudaGetSymbolAddress((void**)&Vth, g_Vth); cudaGetSymbolAddress((void**)&Vtl, g_Vtl);
    cudaGetSymbolAddress((void**)&qf, g_qf);   cudaGetSymbolAddress((void**)&kf, g_kf);
    cudaGetSymbolAddress((void**)&vf, g_vf);

    // idx 0: weight transposes + hidden split, one launch (grid.z = 5)
    transpose_all<<<dim3(HIDDEN / 32, HIDDEN / 32, 5), dim3(32, 8)>>>(
        Wq, Wk, Wv, Wo, hidden,
        Wqh, Wql, Wkh, Wkl, Wvh, Wvl, Woh, Wol, Hh, Hl);

    // idx 1: merged Q/K/V projection (wave-packed)
    cudaFuncSetAttribute(gemm_qkv, cudaFuncAttributeMaxDynamicSharedMemorySize, GEMM_SMEM);
    cudaFuncSetAttribute(gemm_bf16x3, cudaFuncAttributeMaxDynamicSharedMemorySize, GEMM_SMEM);
    gemm_qkv<<<dim3(24, MROWS / 128), 256, GEMM_SMEM>>>(
        Hh, Hl, Wqh, Wql, Wkh, Wkl, Wvh, Wvl, bq, bk, bv, qf, kf, vf);

    // idx 2: merged RoPE-split + V-transpose-split
    prep_rope_vt<<<MROWS / 2 + 2048, 256>>>(posids, qf, kf, vf, Qh, Ql, Kh, Kl, Vth, Vtl);

    // idx 3: attention — LPT grid, hoisted Q frags
    cudaFuncSetAttribute(attn_mma, cudaFuncAttributeMaxDynamicSharedMemorySize, ATTN_SMEM);
    attn_mma<<<dim3(NHEADS * BATCH, SEQ / 128), 256, ATTN_SMEM>>>(Qh, Ql, Kh, Kl, Vth, Vtl, Ah, Al);

    // idx 4: output projection
    gemm_bf16x3<<<dim3(HIDDEN / 128, MROWS / 128), 256, GEMM_SMEM>>>(Ah, Al, Woh, Wol, bo, out, MROWS, HIDDEN, HIDDEN);
}